// round 2
// baseline (speedup 1.0000x reference)
#include <cuda_runtime.h>
#include <cstdint>

#define B_   64
#define S_   1024
#define IN_  512
#define H4_  512
#define G_   2048
#define NCTA2 128

__device__ float    g_gx[(size_t)S_ * G_ * B_];   // [s][n][b]
__device__ float    g_hbuf[2][H4_ * B_];          // [k][b]
__device__ unsigned g_bar;

__device__ __forceinline__ float2 ffma2(float2 a, float2 b, float2 c) {
    float2 d;
    asm("fma.rn.f32x2 %0, %1, %2, %3;"
        : "=l"(reinterpret_cast<unsigned long long&>(d))
        : "l"(reinterpret_cast<unsigned long long&>(a)),
          "l"(reinterpret_cast<unsigned long long&>(b)),
          "l"(reinterpret_cast<unsigned long long&>(c)));
    return d;
}

__global__ void reset_kernel() { g_bar = 0u; }

// ---------------- Phase 1: gates_x = X @ Wi^T + bi ----------------
#define LDA1 132
__global__ __launch_bounds__(256, 2) void gemm_x_kernel(
    const float* __restrict__ X, const float* __restrict__ Wi,
    const float* __restrict__ bi)
{
    extern __shared__ float sm[];
    float* As = sm;
    float* Bs = sm + 16 * LDA1;

    const int tid = threadIdx.x;
    const int n0  = blockIdx.x * 128;
    const int bm  = blockIdx.y;

    const int r0 = tid >> 2,         kq0 = (tid & 3) * 4;
    const int r1 = (tid + 256) >> 2, kq1 = kq0;

    const float* Ap0 = X + (size_t)(r0 & 63) * (S_ * IN_) + (size_t)(bm * 2 + (r0 >> 6)) * IN_ + kq0;
    const float* Ap1 = X + (size_t)(r1 & 63) * (S_ * IN_) + (size_t)(bm * 2 + (r1 >> 6)) * IN_ + kq1;
    const float* Bp0 = Wi + (size_t)(n0 + r0) * IN_ + kq0;
    const float* Bp1 = Wi + (size_t)(n0 + r1) * IN_ + kq1;

    float4 pa0 = *(const float4*)Ap0;
    float4 pa1 = *(const float4*)Ap1;
    float4 pb0 = *(const float4*)Bp0;
    float4 pb1 = *(const float4*)Bp1;

    const int ty = tid >> 4;
    const int tx = tid & 15;

    float2 acc[4][8];
#pragma unroll
    for (int i = 0; i < 4; i++)
#pragma unroll
        for (int j = 0; j < 8; j++) acc[i][j] = make_float2(0.f, 0.f);

    for (int kt = 0; kt < 32; kt++) {
        __syncthreads();
        As[(kq0 + 0) * LDA1 + r0] = pa0.x;
        As[(kq0 + 1) * LDA1 + r0] = pa0.y;
        As[(kq0 + 2) * LDA1 + r0] = pa0.z;
        As[(kq0 + 3) * LDA1 + r0] = pa0.w;
        As[(kq1 + 0) * LDA1 + r1] = pa1.x;
        As[(kq1 + 1) * LDA1 + r1] = pa1.y;
        As[(kq1 + 2) * LDA1 + r1] = pa1.z;
        As[(kq1 + 3) * LDA1 + r1] = pa1.w;
        Bs[(kq0 + 0) * LDA1 + r0] = pb0.x;
        Bs[(kq0 + 1) * LDA1 + r0] = pb0.y;
        Bs[(kq0 + 2) * LDA1 + r0] = pb0.z;
        Bs[(kq0 + 3) * LDA1 + r0] = pb0.w;
        Bs[(kq1 + 0) * LDA1 + r1] = pb1.x;
        Bs[(kq1 + 1) * LDA1 + r1] = pb1.y;
        Bs[(kq1 + 2) * LDA1 + r1] = pb1.z;
        Bs[(kq1 + 3) * LDA1 + r1] = pb1.w;
        __syncthreads();

        if (kt < 31) {
            Ap0 += 16; Ap1 += 16; Bp0 += 16; Bp1 += 16;
            pa0 = *(const float4*)Ap0;
            pa1 = *(const float4*)Ap1;
            pb0 = *(const float4*)Bp0;
            pb1 = *(const float4*)Bp1;
        }

#pragma unroll 4
        for (int kk = 0; kk < 16; kk++) {
            float4 a0 = *(const float4*)&As[kk * LDA1 + ty * 8];
            float4 a1 = *(const float4*)&As[kk * LDA1 + ty * 8 + 4];
            float4 b0 = *(const float4*)&Bs[kk * LDA1 + tx * 8];
            float4 b1 = *(const float4*)&Bs[kk * LDA1 + tx * 8 + 4];
            float2 a2[4] = { make_float2(a0.x, a0.y), make_float2(a0.z, a0.w),
                             make_float2(a1.x, a1.y), make_float2(a1.z, a1.w) };
            float bb[8] = { b0.x, b0.y, b0.z, b0.w, b1.x, b1.y, b1.z, b1.w };
#pragma unroll
            for (int i2 = 0; i2 < 4; i2++)
#pragma unroll
                for (int j = 0; j < 8; j++)
                    acc[i2][j] = ffma2(a2[i2], make_float2(bb[j], bb[j]), acc[i2][j]);
        }
    }

    float bias[8];
#pragma unroll
    for (int j = 0; j < 8; j++) bias[j] = bi[n0 + tx * 8 + j];

    __syncthreads();
    float* st = sm;   // [128 n][stride 132] holds m
#pragma unroll
    for (int i2 = 0; i2 < 4; i2++)
#pragma unroll
        for (int j = 0; j < 8; j++) {
            st[(tx * 8 + j) * 132 + ty * 8 + i2 * 2 + 0] = acc[i2][j].x + bias[j];
            st[(tx * 8 + j) * 132 + ty * 8 + i2 * 2 + 1] = acc[i2][j].y + bias[j];
        }
    __syncthreads();

#pragma unroll 4
    for (int it = 0; it < 64; it++) {
        int flat = it * 256 + tid;
        int n = flat >> 7, r = flat & 127;
        size_t o = ((size_t)(bm * 2 + (r >> 6)) * G_ + (n0 + n)) * B_ + (r & 63);
        g_gx[o] = st[n * 132 + r];
    }
}

// ---------------- Phase 2: recurrence ----------------
__global__ __launch_bounds__(256) void lstm_kernel(
    const float* __restrict__ Wh, const float* __restrict__ bh,
    float* __restrict__ out)
{
    extern __shared__ float sm[];
    float* hs  = sm;               // [512][64]
    float* ws  = sm + H4_ * B_;    // [16][512]
    float* red = ws + 16 * H4_;    // 1024 floats

    const int tid = threadIdx.x;
    const int j0  = blockIdx.x * 4;

    for (int i = tid; i < 16 * H4_; i += 256) {
        int cidx = i >> 9, k = i & 511;
        int gg = cidx >> 2, jj = cidx & 3;
        ws[i] = Wh[((size_t)(gg * H4_ + j0 + jj)) * H4_ + k];
    }
    for (int i = tid; i < H4_ * B_; i += 256) hs[i] = 0.f;
    __syncthreads();

    const int ks = tid >> 7;
    const int jj = (tid >> 5) & 3;
    const int p  = tid & 31;

    const float* wI = ws + (0 * 4 + jj) * H4_;
    const float* wF = ws + (1 * 4 + jj) * H4_;
    const float* wG = ws + (2 * 4 + jj) * H4_;
    const float* wO = ws + (3 * 4 + jj) * H4_;

    const float bI = bh[0 * H4_ + j0 + jj];
    const float bF = bh[1 * H4_ + j0 + jj];
    const float bG = bh[2 * H4_ + j0 + jj];
    const float bO = bh[3 * H4_ + j0 + jj];

    float2 c2 = make_float2(0.f, 0.f);
    const float2* hs2 = (const float2*)hs;
    float2* redp = (float2*)red;
    const unsigned nctas = gridDim.x;

    for (int t = 0; t < S_; t++) {
        float2 aI = make_float2(0.f, 0.f), aF = aI, aG = aI, aO = aI;
        const int kb = ks << 8;
#pragma unroll 2
        for (int k = 0; k < 256; k += 4) {
            const int kk = kb + k;
            float4 wi4 = *(const float4*)(wI + kk);
            float4 wf4 = *(const float4*)(wF + kk);
            float4 wg4 = *(const float4*)(wG + kk);
            float4 wo4 = *(const float4*)(wO + kk);
            float2 h0 = hs2[(kk + 0) * 32 + p];
            float2 h1 = hs2[(kk + 1) * 32 + p];
            float2 h2 = hs2[(kk + 2) * 32 + p];
            float2 h3 = hs2[(kk + 3) * 32 + p];
            aI = ffma2(make_float2(wi4.x, wi4.x), h0, aI);
            aF = ffma2(make_float2(wf4.x, wf4.x), h0, aF);
            aG = ffma2(make_float2(wg4.x, wg4.x), h0, aG);
            aO = ffma2(make_float2(wo4.x, wo4.x), h0, aO);
            aI = ffma2(make_float2(wi4.y, wi4.y), h1, aI);
            aF = ffma2(make_float2(wf4.y, wf4.y), h1, aF);
            aG = ffma2(make_float2(wg4.y, wg4.y), h1, aG);
            aO = ffma2(make_float2(wo4.y, wo4.y), h1, aO);
            aI = ffma2(make_float2(wi4.z, wi4.z), h2, aI);
            aF = ffma2(make_float2(wf4.z, wf4.z), h2, aF);
            aG = ffma2(make_float2(wg4.z, wg4.z), h2, aG);
            aO = ffma2(make_float2(wo4.z, wo4.z), h2, aO);
            aI = ffma2(make_float2(wi4.w, wi4.w), h3, aI);
            aF = ffma2(make_float2(wf4.w, wf4.w), h3, aF);
            aG = ffma2(make_float2(wg4.w, wg4.w), h3, aG);
            aO = ffma2(make_float2(wo4.w, wo4.w), h3, aO);
        }

        if (ks == 1) {
            const int base = (jj * 32 + p) * 4;
            redp[base + 0] = aI; redp[base + 1] = aF;
            redp[base + 2] = aG; redp[base + 3] = aO;
        }
        __syncthreads();

        if (ks == 0) {
            const int base = (jj * 32 + p) * 4;
            float2 rI = redp[base + 0], rF = redp[base + 1];
            float2 rG = redp[base + 2], rO = redp[base + 3];
            const float2* gx2 = (const float2*)(g_gx + (size_t)t * (G_ * B_));
            float2 gI = gx2[(0 * H4_ + j0 + jj) * 32 + p];
            float2 gF = gx2[(1 * H4_ + j0 + jj) * 32 + p];
            float2 gG = gx2[(2 * H4_ + j0 + jj) * 32 + p];
            float2 gO = gx2[(3 * H4_ + j0 + jj) * 32 + p];

            float pi[2] = { aI.x + rI.x + gI.x + bI, aI.y + rI.y + gI.y + bI };
            float pf[2] = { aF.x + rF.x + gF.x + bF, aF.y + rF.y + gF.y + bF };
            float pg[2] = { aG.x + rG.x + gG.x + bG, aG.y + rG.y + gG.y + bG };
            float po[2] = { aO.x + rO.x + gO.x + bO, aO.y + rO.y + gO.y + bO };

            float* hnext = g_hbuf[(t + 1) & 1];
#pragma unroll
            for (int cpt = 0; cpt < 2; cpt++) {
                float iv = 1.f / (1.f + __expf(-pi[cpt]));
                float fv = 1.f / (1.f + __expf(-pf[cpt]));
                float gv = tanhf(pg[cpt]);
                float ov = 1.f / (1.f + __expf(-po[cpt]));
                float cc = (cpt ? c2.y : c2.x);
                cc = fv * cc + iv * gv;
                float hh = ov * tanhf(cc);
                if (cpt) c2.y = cc; else c2.x = cc;
                const int b = 2 * p + cpt;
                hnext[(j0 + jj) * B_ + b] = hh;
                out[((size_t)b * S_ + t) * H4_ + (j0 + jj)] = hh;
                if (t == S_ - 1) {
                    out[(size_t)B_ * S_ * H4_ + (size_t)b * H4_ + (j0 + jj)] = hh;
                    out[(size_t)B_ * S_ * H4_ + (size_t)B_ * H4_ + (size_t)b * H4_ + (j0 + jj)] = cc;
                }
            }
        }

        __threadfence();
        __syncthreads();
        if (tid == 0) {
            atomicAdd(&g_bar, 1u);
            const unsigned tgt = (unsigned)(t + 1) * nctas;
            while (*(volatile unsigned*)&g_bar < tgt) __nanosleep(64);
        }
        __syncthreads();

        const float4* src = (const float4*)g_hbuf[(t + 1) & 1];
        float4* dst = (float4*)hs;
#pragma unroll 4
        for (int i = tid; i < (H4_ * B_) / 4; i += 256)
            dst[i] = __ldcg(src + i);
        __syncthreads();
    }
}

extern "C" void kernel_launch(void* const* d_in, const int* in_sizes, int n_in,
                              void* d_out, int out_size) {
    const float* X  = (const float*)d_in[0];
    const float* Wi = (const float*)d_in[1];
    const float* Wh = (const float*)d_in[2];
    const float* bi = (const float*)d_in[3];
    const float* bh = (const float*)d_in[4];
    float* out = (float*)d_out;

    cudaFuncSetAttribute(gemm_x_kernel, cudaFuncAttributeMaxDynamicSharedMemorySize, 67584);
    cudaFuncSetAttribute(lstm_kernel,  cudaFuncAttributeMaxDynamicSharedMemorySize, 167936);

    reset_kernel<<<1, 1>>>();
    gemm_x_kernel<<<dim3(16, 512), 256, 67584>>>(X, Wi, bi);
    lstm_kernel<<<NCTA2, 256, 167936>>>(Wh, bh, out);
}

// round 3
// speedup vs baseline: 1.1019x; 1.1019x over previous
#include <cuda_runtime.h>
#include <cstdint>

#define B_   64
#define S_   1024
#define IN_  512
#define H4_  512
#define G_   2048
#define NCTA2 128

__device__ float    g_gx[(size_t)S_ * G_ * B_];   // [s][n][b]
__device__ float    g_hbuf[2][H4_ * B_];          // [j][b]
__device__ unsigned g_cnt;
__device__ unsigned g_gen;

__device__ __forceinline__ float2 ffma2(float2 a, float2 b, float2 c) {
    float2 d;
    asm("fma.rn.f32x2 %0, %1, %2, %3;"
        : "=l"(reinterpret_cast<unsigned long long&>(d))
        : "l"(reinterpret_cast<unsigned long long&>(a)),
          "l"(reinterpret_cast<unsigned long long&>(b)),
          "l"(reinterpret_cast<unsigned long long&>(c)));
    return d;
}

// ---------------- Phase 1: gates_x = X @ Wi^T + bi ----------------
#define LDA1 132
__global__ __launch_bounds__(256, 2) void gemm_x_kernel(
    const float* __restrict__ X, const float* __restrict__ Wi,
    const float* __restrict__ bi)
{
    extern __shared__ float sm[];
    float* As = sm;
    float* Bs = sm + 16 * LDA1;

    const int tid = threadIdx.x;
    const int n0  = blockIdx.x * 128;
    const int bm  = blockIdx.y;

    const int r0 = tid >> 2,         kq0 = (tid & 3) * 4;
    const int r1 = (tid + 256) >> 2, kq1 = kq0;

    const float* Ap0 = X + (size_t)(r0 & 63) * (S_ * IN_) + (size_t)(bm * 2 + (r0 >> 6)) * IN_ + kq0;
    const float* Ap1 = X + (size_t)(r1 & 63) * (S_ * IN_) + (size_t)(bm * 2 + (r1 >> 6)) * IN_ + kq1;
    const float* Bp0 = Wi + (size_t)(n0 + r0) * IN_ + kq0;
    const float* Bp1 = Wi + (size_t)(n0 + r1) * IN_ + kq1;

    float4 pa0 = *(const float4*)Ap0;
    float4 pa1 = *(const float4*)Ap1;
    float4 pb0 = *(const float4*)Bp0;
    float4 pb1 = *(const float4*)Bp1;

    const int ty = tid >> 4;
    const int tx = tid & 15;

    float2 acc[4][8];
#pragma unroll
    for (int i = 0; i < 4; i++)
#pragma unroll
        for (int j = 0; j < 8; j++) acc[i][j] = make_float2(0.f, 0.f);

    for (int kt = 0; kt < 32; kt++) {
        __syncthreads();
        As[(kq0 + 0) * LDA1 + r0] = pa0.x;
        As[(kq0 + 1) * LDA1 + r0] = pa0.y;
        As[(kq0 + 2) * LDA1 + r0] = pa0.z;
        As[(kq0 + 3) * LDA1 + r0] = pa0.w;
        As[(kq1 + 0) * LDA1 + r1] = pa1.x;
        As[(kq1 + 1) * LDA1 + r1] = pa1.y;
        As[(kq1 + 2) * LDA1 + r1] = pa1.z;
        As[(kq1 + 3) * LDA1 + r1] = pa1.w;
        Bs[(kq0 + 0) * LDA1 + r0] = pb0.x;
        Bs[(kq0 + 1) * LDA1 + r0] = pb0.y;
        Bs[(kq0 + 2) * LDA1 + r0] = pb0.z;
        Bs[(kq0 + 3) * LDA1 + r0] = pb0.w;
        Bs[(kq1 + 0) * LDA1 + r1] = pb1.x;
        Bs[(kq1 + 1) * LDA1 + r1] = pb1.y;
        Bs[(kq1 + 2) * LDA1 + r1] = pb1.z;
        Bs[(kq1 + 3) * LDA1 + r1] = pb1.w;
        __syncthreads();

        if (kt < 31) {
            Ap0 += 16; Ap1 += 16; Bp0 += 16; Bp1 += 16;
            pa0 = *(const float4*)Ap0;
            pa1 = *(const float4*)Ap1;
            pb0 = *(const float4*)Bp0;
            pb1 = *(const float4*)Bp1;
        }

#pragma unroll 4
        for (int kk = 0; kk < 16; kk++) {
            float4 a0 = *(const float4*)&As[kk * LDA1 + ty * 8];
            float4 a1 = *(const float4*)&As[kk * LDA1 + ty * 8 + 4];
            float4 b0 = *(const float4*)&Bs[kk * LDA1 + tx * 8];
            float4 b1 = *(const float4*)&Bs[kk * LDA1 + tx * 8 + 4];
            float2 a2[4] = { make_float2(a0.x, a0.y), make_float2(a0.z, a0.w),
                             make_float2(a1.x, a1.y), make_float2(a1.z, a1.w) };
            float bb[8] = { b0.x, b0.y, b0.z, b0.w, b1.x, b1.y, b1.z, b1.w };
#pragma unroll
            for (int i2 = 0; i2 < 4; i2++)
#pragma unroll
                for (int j = 0; j < 8; j++)
                    acc[i2][j] = ffma2(a2[i2], make_float2(bb[j], bb[j]), acc[i2][j]);
        }
    }

    float bias[8];
#pragma unroll
    for (int j = 0; j < 8; j++) bias[j] = bi[n0 + tx * 8 + j];

    __syncthreads();
    float* st = sm;
#pragma unroll
    for (int i2 = 0; i2 < 4; i2++)
#pragma unroll
        for (int j = 0; j < 8; j++) {
            st[(tx * 8 + j) * 132 + ty * 8 + i2 * 2 + 0] = acc[i2][j].x + bias[j];
            st[(tx * 8 + j) * 132 + ty * 8 + i2 * 2 + 1] = acc[i2][j].y + bias[j];
        }
    __syncthreads();

#pragma unroll 4
    for (int it = 0; it < 64; it++) {
        int flat = it * 256 + tid;
        int n = flat >> 7, r = flat & 127;
        size_t o = ((size_t)(bm * 2 + (r >> 6)) * G_ + (n0 + n)) * B_ + (r & 63);
        g_gx[o] = st[n * 132 + r];
    }
}

// ---------------- Phase 2: recurrence ----------------
// 128 CTAs x 256 thr. Thread = (kq 0..3, jg 0..1, p 0..31).
// Covers gates {i,f,g,o} x states {j0+2jg, j0+2jg+1} x batches {2p,2p+1}, k-range 128.
__global__ __launch_bounds__(256, 1) void lstm_kernel(
    const float* __restrict__ Wh, const float* __restrict__ bh,
    float* __restrict__ out)
{
    extern __shared__ float sm[];
    float* hs  = sm;               // [512][64] = 131072 B
    float* ws  = sm + H4_ * B_;    // [16][512] =  32768 B
    float* red = ws + 16 * H4_;    // 4096 floats = 16384 B

    const int tid = threadIdx.x;
    const int j0  = blockIdx.x * 4;

    for (int i = tid; i < 16 * H4_; i += 256) {
        int cidx = i >> 9, k = i & 511;
        int gg = cidx >> 2, jj = cidx & 3;
        ws[i] = Wh[((size_t)(gg * H4_ + j0 + jj)) * H4_ + k];
    }
    for (int i = tid; i < H4_ * B_; i += 256) hs[i] = 0.f;
    __syncthreads();

    const int kq = tid >> 6;
    const int jg = (tid >> 5) & 1;
    const int p  = tid & 31;
    const int kb = kq << 7;

    float bb_[8];
    if (tid < 64) {
#pragma unroll
        for (int g = 0; g < 4; g++)
#pragma unroll
            for (int s = 0; s < 2; s++)
                bb_[g * 2 + s] = bh[g * H4_ + j0 + jg * 2 + s];
    }

    float2 cst[2] = { make_float2(0.f, 0.f), make_float2(0.f, 0.f) };
    const float2* hs2 = (const float2*)hs;
    float2* red2 = (float2*)red;

    for (int t = 0; t < S_; t++) {
        // prefetch gx(t) (consumed after reduction; hidden under GEMV)
        float2 gx[8];
        if (tid < 64) {
            const float2* gxp = (const float2*)(g_gx + (size_t)t * (G_ * B_));
#pragma unroll
            for (int g = 0; g < 4; g++)
#pragma unroll
                for (int s = 0; s < 2; s++)
                    gx[g * 2 + s] = gxp[(g * H4_ + j0 + jg * 2 + s) * 32 + p];
        }

        // GEMV over k-range [kb, kb+128)
        float2 acc[8];
#pragma unroll
        for (int r = 0; r < 8; r++) acc[r] = make_float2(0.f, 0.f);
#pragma unroll 2
        for (int kc = 0; kc < 128; kc += 4) {
            const int kk = kb + kc;
            float4 wv[8];
#pragma unroll
            for (int r = 0; r < 8; r++) {
                int g = r >> 1, s = r & 1;
                wv[r] = *(const float4*)&ws[(g * 4 + jg * 2 + s) * H4_ + kk];
            }
            float2 h0 = hs2[(kk + 0) * 32 + p];
            float2 h1 = hs2[(kk + 1) * 32 + p];
            float2 h2 = hs2[(kk + 2) * 32 + p];
            float2 h3 = hs2[(kk + 3) * 32 + p];
#pragma unroll
            for (int r = 0; r < 8; r++) {
                acc[r] = ffma2(make_float2(wv[r].x, wv[r].x), h0, acc[r]);
                acc[r] = ffma2(make_float2(wv[r].y, wv[r].y), h1, acc[r]);
                acc[r] = ffma2(make_float2(wv[r].z, wv[r].z), h2, acc[r]);
                acc[r] = ffma2(make_float2(wv[r].w, wv[r].w), h3, acc[r]);
            }
        }

        if (kq) {
#pragma unroll
            for (int r = 0; r < 8; r++)
                red2[(r * 4 + kq) * 64 + jg * 32 + p] = acc[r];
        }
        __syncthreads();

        float hsv[2][2];
        if (tid < 64) {
#pragma unroll
            for (int r = 0; r < 8; r++) {
                float2 x1 = red2[(r * 4 + 1) * 64 + jg * 32 + p];
                float2 x2 = red2[(r * 4 + 2) * 64 + jg * 32 + p];
                float2 x3 = red2[(r * 4 + 3) * 64 + jg * 32 + p];
                acc[r].x += x1.x + x2.x + x3.x;
                acc[r].y += x1.y + x2.y + x3.y;
            }
            float* hnext = g_hbuf[(t + 1) & 1];
#pragma unroll
            for (int s = 0; s < 2; s++) {
                float pre[4][2];
#pragma unroll
                for (int g = 0; g < 4; g++) {
                    pre[g][0] = acc[g * 2 + s].x + gx[g * 2 + s].x + bb_[g * 2 + s];
                    pre[g][1] = acc[g * 2 + s].y + gx[g * 2 + s].y + bb_[g * 2 + s];
                }
#pragma unroll
                for (int cpt = 0; cpt < 2; cpt++) {
                    float iv = 1.f / (1.f + __expf(-pre[0][cpt]));
                    float fv = 1.f / (1.f + __expf(-pre[1][cpt]));
                    float gv = tanhf(pre[2][cpt]);
                    float ov = 1.f / (1.f + __expf(-pre[3][cpt]));
                    float c = cpt ? cst[s].y : cst[s].x;
                    c = fv * c + iv * gv;
                    float hh = ov * tanhf(c);
                    if (cpt) cst[s].y = c; else cst[s].x = c;
                    hsv[s][cpt] = hh;
                    const int b = 2 * p + cpt;
                    const int j = j0 + jg * 2 + s;
                    hnext[j * B_ + b] = hh;
                    if (t == S_ - 1) {
                        out[(size_t)B_ * S_ * H4_ + (size_t)b * H4_ + j] = hh;
                        out[(size_t)B_ * S_ * H4_ + (size_t)B_ * H4_ + (size_t)b * H4_ + j] = c;
                    }
                }
            }
            __threadfence();
        }
        __syncthreads();

        // barrier arrive (skip on last step)
        unsigned g0 = 0u; bool i_release = false;
        if (t < S_ - 1 && tid == 0) {
            g0 = __ldcg(&g_gen);
            unsigned a = atomicAdd(&g_cnt, 1u);
            if (a == NCTA2 - 1u) {
                atomicExch(&g_cnt, 0u);
                __threadfence();
                atomicAdd(&g_gen, 1u);
                i_release = true;
            }
        }

        // out stores overlap the spin
        if (tid < 64) {
#pragma unroll
            for (int cpt = 0; cpt < 2; cpt++) {
                const int b = 2 * p + cpt;
                float2 v = make_float2(hsv[0][cpt], hsv[1][cpt]);
                *(float2*)&out[((size_t)b * S_ + t) * H4_ + j0 + jg * 2] = v;
            }
        }

        if (t < S_ - 1) {
            if (tid == 0 && !i_release) {
                while (__ldcg(&g_gen) == g0) __nanosleep(32);
            }
            __syncthreads();
            const float4* src = (const float4*)g_hbuf[(t + 1) & 1];
            float4* dst = (float4*)hs;
#pragma unroll 4
            for (int i = tid; i < (H4_ * B_) / 4; i += 256)
                dst[i] = __ldcg(src + i);
            __syncthreads();
        }
    }
}

extern "C" void kernel_launch(void* const* d_in, const int* in_sizes, int n_in,
                              void* d_out, int out_size) {
    const float* X  = (const float*)d_in[0];
    const float* Wi = (const float*)d_in[1];
    const float* Wh = (const float*)d_in[2];
    const float* bi = (const float*)d_in[3];
    const float* bh = (const float*)d_in[4];
    float* out = (float*)d_out;

    cudaFuncSetAttribute(gemm_x_kernel, cudaFuncAttributeMaxDynamicSharedMemorySize, 67584);
    cudaFuncSetAttribute(lstm_kernel,  cudaFuncAttributeMaxDynamicSharedMemorySize, 180224);

    gemm_x_kernel<<<dim3(16, 512), 256, 67584>>>(X, Wi, bi);
    lstm_kernel<<<NCTA2, 256, 180224>>>(Wh, bh, out);
}

// round 12
// speedup vs baseline: 1.3043x; 1.1837x over previous
#include <cuda_runtime.h>
#include <cuda_fp16.h>
#include <cstdint>

#define B_   64
#define S_   1024
#define IN_  512
#define H4_  512
#define G_   2048
#define NCTA2 128
#define K2_  1536
#define NCH_ 24

__device__ float    g_gx[(size_t)S_ * G_ * B_];   // [s][n][b]
__device__ __half   g_a2[(size_t)S_ * B_ * K2_];  // [m=s*64+b][k']
__device__ __half   g_b2[(size_t)G_ * K2_];       // [n][k']
__device__ float    g_hbuf[2][H4_ * B_];
__device__ unsigned g_cnt;
__device__ unsigned g_gen;

__device__ __forceinline__ float2 ffma2(float2 a, float2 b, float2 c) {
    float2 d;
    asm("fma.rn.f32x2 %0, %1, %2, %3;"
        : "=l"(reinterpret_cast<unsigned long long&>(d))
        : "l"(reinterpret_cast<unsigned long long&>(a)),
          "l"(reinterpret_cast<unsigned long long&>(b)),
          "l"(reinterpret_cast<unsigned long long&>(c)));
    return d;
}

__device__ __forceinline__ uint32_t smem_u32(const void* p) {
    uint32_t a;
    asm("{ .reg .u64 t; cvta.to.shared.u64 t, %1; cvt.u32.u64 %0, t; }" : "=r"(a) : "l"(p));
    return a;
}
#define SW128(x) ((x) ^ (((x) >> 3) & 0x70))

#define LDSM_X4(r0, r1, r2, r3, addr) \
    asm volatile("ldmatrix.sync.aligned.m8n8.x4.shared.b16 {%0,%1,%2,%3}, [%4];" \
        : "=r"(r0), "=r"(r1), "=r"(r2), "=r"(r3) : "r"(addr))

#define MMA16816(d, a, b) \
    asm volatile("mma.sync.aligned.m16n8k16.row.col.f32.f16.f16.f32 " \
        "{%0,%1,%2,%3}, {%4,%5,%6,%7}, {%8,%9}, {%0,%1,%2,%3};" \
        : "+f"(d[0]), "+f"(d[1]), "+f"(d[2]), "+f"(d[3]) \
        : "r"(a[0]), "r"(a[1]), "r"(a[2]), "r"(a[3]), "r"(b[0]), "r"(b[1]))

#define CP_ASYNC16(dst, src) \
    asm volatile("cp.async.cg.shared.global [%0], [%1], 16;" :: "r"(dst), "l"(src) : "memory")
#define CP_COMMIT() asm volatile("cp.async.commit_group;" ::: "memory")
#define CP_WAIT1()  asm volatile("cp.async.wait_group 1;" ::: "memory")
#define CP_WAIT0()  asm volatile("cp.async.wait_group 0;" ::: "memory")

// ---------------- hi/lo fp16 split conversions ----------------
__global__ __launch_bounds__(256) void conv_a_kernel(const float* __restrict__ X) {
    size_t gtid = (size_t)blockIdx.x * 256 + threadIdx.x;   // 8388608
    int k4 = (int)(gtid & 127);
    size_t row = gtid >> 7;              // b*1024 + s
    int b = (int)(row >> 10), s = (int)(row & 1023);
    float4 x = *(const float4*)(X + row * 512 + k4 * 4);
    float xv[4] = { x.x, x.y, x.z, x.w };
    __half h[4], l[4];
#pragma unroll
    for (int i = 0; i < 4; i++) {
        h[i] = __float2half_rn(xv[i]);
        l[i] = __float2half_rn(xv[i] - __half2float(h[i]));
    }
    size_t m = (size_t)s * 64 + b;
    __half* base = g_a2 + m * K2_ + k4 * 4;
    __half2 h01 = __halves2half2(h[0], h[1]), h23 = __halves2half2(h[2], h[3]);
    __half2 l01 = __halves2half2(l[0], l[1]), l23 = __halves2half2(l[2], l[3]);
    *(__half2*)(base + 0) = h01;        *(__half2*)(base + 2) = h23;
    *(__half2*)(base + 512) = h01;      *(__half2*)(base + 514) = h23;
    *(__half2*)(base + 1024) = l01;     *(__half2*)(base + 1026) = l23;
}

__global__ __launch_bounds__(256) void conv_b_kernel(const float* __restrict__ Wi) {
    size_t gtid = (size_t)blockIdx.x * 256 + threadIdx.x;   // 262144
    int k4 = (int)(gtid & 127);
    size_t n = gtid >> 7;
    float4 x = *(const float4*)(Wi + n * 512 + k4 * 4);
    float xv[4] = { x.x, x.y, x.z, x.w };
    __half h[4], l[4];
#pragma unroll
    for (int i = 0; i < 4; i++) {
        h[i] = __float2half_rn(xv[i]);
        l[i] = __float2half_rn(xv[i] - __half2float(h[i]));
    }
    __half* base = g_b2 + n * K2_ + k4 * 4;
    __half2 h01 = __halves2half2(h[0], h[1]), h23 = __halves2half2(h[2], h[3]);
    __half2 l01 = __halves2half2(l[0], l[1]), l23 = __halves2half2(l[2], l[3]);
    *(__half2*)(base + 0) = h01;        *(__half2*)(base + 2) = h23;
    *(__half2*)(base + 512) = l01;      *(__half2*)(base + 514) = l23;
    *(__half2*)(base + 1024) = h01;     *(__half2*)(base + 1026) = h23;
}

// ---------------- Phase 1: HMMA GEMM, tile M=128 N=128 K=1536 ----------------
// smem: A buf0 @0, A buf1 @16384, B buf0 @32768, B buf1 @49152 (64KB);
// epilogue stage reuses [0, 67584).
#define SMEM_GEMM 67584

__global__ __launch_bounds__(256, 2) void gemm_hmma_kernel(const float* __restrict__ bi) {
    extern __shared__ char smp[];
    const uint32_t sb = smem_u32(smp);
    const int tid = threadIdx.x, wid = tid >> 5, lane = tid & 31;
    const int n0 = blockIdx.x * 128;
    const int bm = blockIdx.y;            // m0 = bm*128

    const __half* Abase = g_a2 + (size_t)bm * 128 * K2_;
    const __half* Bbase = g_b2 + (size_t)n0 * K2_;

    const int warp_m = (wid & 1) * 64 + (wid >> 2) * 32;  // 4 m-slots
    const int warp_n = ((wid >> 1) & 1) * 64;             // 2 n-slots

    float acc[2][8][4];
#pragma unroll
    for (int mt = 0; mt < 2; mt++)
#pragma unroll
        for (int nt = 0; nt < 8; nt++)
#pragma unroll
            for (int q = 0; q < 4; q++) acc[mt][nt][q] = 0.f;

    const int lrow = tid >> 3;      // 0..31 per 256-thread pass? (flat>>3 below)
    (void)lrow;

    // issue cp.async for chunk c into buffer buf
    auto issue = [&](int c, int buf) {
        const int kc = c * 64;
#pragma unroll
        for (int i = 0; i < 4; i++) {
            int flat = i * 256 + tid, row = flat >> 3, c16 = flat & 7;
            uint32_t da = sb + buf * 16384 + SW128(row * 128 + c16 * 16);
            CP_ASYNC16(da, (const void*)(Abase + (size_t)row * K2_ + kc + c16 * 8));
        }
#pragma unroll
        for (int i = 0; i < 4; i++) {
            int flat = i * 256 + tid, row = flat >> 3, c16 = flat & 7;
            uint32_t db = sb + 32768 + buf * 16384 + SW128(row * 128 + c16 * 16);
            CP_ASYNC16(db, (const void*)(Bbase + (size_t)row * K2_ + kc + c16 * 8));
        }
        CP_COMMIT();
    };

    issue(0, 0);

    for (int c = 0; c < NCH_; c++) {
        const int buf = c & 1;
        if (c + 1 < NCH_) { issue(c + 1, buf ^ 1); CP_WAIT1(); }
        else              { CP_WAIT0(); }
        __syncthreads();

        const uint32_t Aoff = sb + buf * 16384;
        const uint32_t Boff = sb + 32768 + buf * 16384;
        const int arow = warp_m + (lane & 15);
        const int brow = warp_n + (lane & 7) + ((lane & 16) ? 8 : 0);
        const int akb  = (lane & 16) ? 16 : 0;
        const int bkb  = (lane & 8) ? 16 : 0;

#pragma unroll
        for (int ks = 0; ks < 4; ks++) {
            uint32_t a[2][4];
#pragma unroll
            for (int mt = 0; mt < 2; mt++)
                LDSM_X4(a[mt][0], a[mt][1], a[mt][2], a[mt][3],
                        Aoff + SW128((arow + mt * 16) * 128 + ks * 32 + akb));
            uint32_t b[8][2];
#pragma unroll
            for (int bt = 0; bt < 4; bt++) {
                uint32_t r0, r1, r2, r3;
                LDSM_X4(r0, r1, r2, r3,
                        Boff + SW128((brow + bt * 16) * 128 + ks * 32 + bkb));
                b[bt * 2][0] = r0; b[bt * 2][1] = r1;
                b[bt * 2 + 1][0] = r2; b[bt * 2 + 1][1] = r3;
            }
#pragma unroll
            for (int mt = 0; mt < 2; mt++)
#pragma unroll
                for (int nt = 0; nt < 8; nt++)
                    MMA16816(acc[mt][nt], a[mt], b[nt]);
        }
        __syncthreads();
    }

    // epilogue: stage [n][m] stride 132, then coalesced store to g_gx[s][n][b] + bias
    float* st = (float*)smp;
#pragma unroll
    for (int mt = 0; mt < 2; mt++)
#pragma unroll
        for (int nt = 0; nt < 8; nt++) {
            const int m = warp_m + mt * 16 + (lane >> 2);
            const int n = warp_n + nt * 8 + 2 * (lane & 3);
            st[n * 132 + m]           = acc[mt][nt][0];
            st[(n + 1) * 132 + m]     = acc[mt][nt][1];
            st[n * 132 + m + 8]       = acc[mt][nt][2];
            st[(n + 1) * 132 + m + 8] = acc[mt][nt][3];
        }
    __syncthreads();

#pragma unroll 4
    for (int it = 0; it < 64; it++) {
        int flat = it * 256 + tid;
        int m = flat & 127, n = flat >> 7;
        float v = st[n * 132 + m] + __ldg(bi + n0 + n);
        g_gx[(size_t)(bm * 2 + (m >> 6)) * (G_ * B_) + (size_t)(n0 + n) * B_ + (m & 63)] = v;
    }
}

// ---------------- Phase 2: recurrence ----------------
__global__ __launch_bounds__(256, 1) void lstm_kernel(
    const float* __restrict__ Wh, const float* __restrict__ bh,
    float* __restrict__ out)
{
    extern __shared__ float sm[];
    float* hs  = sm;
    float* ws  = sm + H4_ * B_;
    float* red = ws + 16 * H4_;

    const int tid = threadIdx.x;
    const int j0  = blockIdx.x * 4;

    for (int i = tid; i < 16 * H4_; i += 256) {
        int cidx = i >> 9, k = i & 511;
        int gg = cidx >> 2, jj = cidx & 3;
        ws[i] = Wh[((size_t)(gg * H4_ + j0 + jj)) * H4_ + k];
    }
    for (int i = tid; i < H4_ * B_; i += 256) hs[i] = 0.f;
    __syncthreads();

    const int kq = tid >> 6;
    const int jg = (tid >> 5) & 1;
    const int p  = tid & 31;
    const int kb = kq << 7;

    float bb_[8];
    if (tid < 64) {
#pragma unroll
        for (int g = 0; g < 4; g++)
#pragma unroll
            for (int s = 0; s < 2; s++)
                bb_[g * 2 + s] = bh[g * H4_ + j0 + jg * 2 + s];
    }

    float2 cst[2] = { make_float2(0.f, 0.f), make_float2(0.f, 0.f) };
    const float2* hs2 = (const float2*)hs;
    float2* red2 = (float2*)red;

    for (int t = 0; t < S_; t++) {
        float2 gx[8];
        if (tid < 64) {
            const float2* gxp = (const float2*)(g_gx + (size_t)t * (G_ * B_));
#pragma unroll
            for (int g = 0; g < 4; g++)
#pragma unroll
                for (int s = 0; s < 2; s++)
                    gx[g * 2 + s] = gxp[(g * H4_ + j0 + jg * 2 + s) * 32 + p];
        }

        float2 acc[8];
#pragma unroll
        for (int r = 0; r < 8; r++) acc[r] = make_float2(0.f, 0.f);
#pragma unroll 2
        for (int kc = 0; kc < 128; kc += 4) {
            const int kk = kb + kc;
            float4 wv[8];
#pragma unroll
            for (int r = 0; r < 8; r++) {
                int g = r >> 1, s = r & 1;
                wv[r] = *(const float4*)&ws[(g * 4 + jg * 2 + s) * H4_ + kk];
            }
            float2 h0 = hs2[(kk + 0) * 32 + p];
            float2 h1 = hs2[(kk + 1) * 32 + p];
            float2 h2 = hs2[(kk + 2) * 32 + p];
            float2 h3 = hs2[(kk + 3) * 32 + p];
#pragma unroll
            for (int r = 0; r < 8; r++) {
                acc[r] = ffma2(make_float2(wv[r].x, wv[r].x), h0, acc[r]);
                acc[r] = ffma2(make_float2(wv[r].y, wv[r].y), h1, acc[r]);
                acc[r] = ffma2(make_float2(wv[r].z, wv[r].z), h2, acc[r]);
                acc[r] = ffma2(make_float2(wv[r].w, wv[r].w), h3, acc[r]);
            }
        }

        if (kq) {
#pragma unroll
            for (int r = 0; r < 8; r++)
                red2[(r * 4 + kq) * 64 + jg * 32 + p] = acc[r];
        }
        __syncthreads();

        float hsv[2][2];
        if (tid < 64) {
#pragma unroll
            for (int r = 0; r < 8; r++) {
                float2 x1 = red2[(r * 4 + 1) * 64 + jg * 32 + p];
                float2 x2 = red2[(r * 4 + 2) * 64 + jg * 32 + p];
                float2 x3 = red2[(r * 4 + 3) * 64 + jg * 32 + p];
                acc[r].x += x1.x + x2.x + x3.x;
                acc[r].y += x1.y + x2.y + x3.y;
            }
            float* hnext = g_hbuf[(t + 1) & 1];
#pragma unroll
            for (int s = 0; s < 2; s++) {
                float pre[4][2];
#pragma unroll
                for (int g = 0; g < 4; g++) {
                    pre[g][0] = acc[g * 2 + s].x + gx[g * 2 + s].x + bb_[g * 2 + s];
                    pre[g][1] = acc[g * 2 + s].y + gx[g * 2 + s].y + bb_[g * 2 + s];
                }
#pragma unroll
                for (int cpt = 0; cpt < 2; cpt++) {
                    float iv = 1.f / (1.f + __expf(-pre[0][cpt]));
                    float fv = 1.f / (1.f + __expf(-pre[1][cpt]));
                    float gv = tanhf(pre[2][cpt]);
                    float ov = 1.f / (1.f + __expf(-pre[3][cpt]));
                    float c = cpt ? cst[s].y : cst[s].x;
                    c = fv * c + iv * gv;
                    float hh = ov * tanhf(c);
                    if (cpt) cst[s].y = c; else cst[s].x = c;
                    hsv[s][cpt] = hh;
                    const int b = 2 * p + cpt;
                    const int j = j0 + jg * 2 + s;
                    hnext[j * B_ + b] = hh;
                    if (t == S_ - 1) {
                        out[(size_t)B_ * S_ * H4_ + (size_t)b * H4_ + j] = hh;
                        out[(size_t)B_ * S_ * H4_ + (size_t)B_ * H4_ + (size_t)b * H4_ + j] = c;
                    }
                }
            }
            __threadfence();
        }
        __syncthreads();

        unsigned g0 = 0u; bool i_release = false;
        if (t < S_ - 1 && tid == 0) {
            g0 = *(volatile unsigned*)&g_gen;
            unsigned a = atomicAdd(&g_cnt, 1u);
            if (a == NCTA2 - 1u) {
                atomicExch(&g_cnt, 0u);
                __threadfence();
                atomicAdd(&g_gen, 1u);
                i_release = true;
            }
        }

        if (tid < 64) {
#pragma unroll
            for (int cpt = 0; cpt < 2; cpt++) {
                const int b = 2 * p + cpt;
                float2 v = make_float2(hsv[0][cpt], hsv[1][cpt]);
                *(float2*)&out[((size_t)b * S_ + t) * H4_ + j0 + jg * 2] = v;
            }
        }

        if (t < S_ - 1) {
            if (tid == 0 && !i_release) {
                while (*(volatile unsigned*)&g_gen == g0) { }
            }
            __syncthreads();
            const float4* src = (const float4*)g_hbuf[(t + 1) & 1];
            float4* dst = (float4*)hs;
#pragma unroll 4
            for (int i = tid; i < (H4_ * B_) / 4; i += 256)
                dst[i] = __ldcg(src + i);
            __syncthreads();
        }
    }
}

extern "C" void kernel_launch(void* const* d_in, const int* in_sizes, int n_in,
                              void* d_out, int out_size) {
    const float* X  = (const float*)d_in[0];
    const float* Wi = (const float*)d_in[1];
    const float* Wh = (const float*)d_in[2];
    const float* bi = (const float*)d_in[3];
    const float* bh = (const float*)d_in[4];
    float* out = (float*)d_out;

    cudaFuncSetAttribute(gemm_hmma_kernel, cudaFuncAttributeMaxDynamicSharedMemorySize, SMEM_GEMM);
    cudaFuncSetAttribute(lstm_kernel, cudaFuncAttributeMaxDynamicSharedMemorySize, 180224);

    conv_a_kernel<<<32768, 256>>>(X);
    conv_b_kernel<<<1024, 256>>>(Wi);
    gemm_hmma_kernel<<<dim3(16, 512), 256, SMEM_GEMM>>>(bi);
    lstm_kernel<<<NCTA2, 256, 180224>>>(Wh, bh, out);
}

// round 13
// speedup vs baseline: 1.6419x; 1.2588x over previous
#include <cuda_runtime.h>
#include <cuda_fp16.h>
#include <cstdint>

#define B_   64
#define S_   1024
#define IN_  512
#define H4_  512
#define G_   2048
#define NCTA2 128
#define K2_  1536
#define NCH_ 24

__device__ float    g_gx[(size_t)S_ * G_ * B_];   // [s][n][b]
__device__ __half   g_a2[(size_t)S_ * B_ * K2_];  // [m=s*64+b][k']
__device__ __half   g_b2[(size_t)G_ * K2_];       // [n][k']
__device__ float    g_hbuf[2][H4_ * B_];          // [j][b]
__device__ unsigned g_cnt;

__device__ __forceinline__ float2 ffma2(float2 a, float2 b, float2 c) {
    float2 d;
    asm("fma.rn.f32x2 %0, %1, %2, %3;"
        : "=l"(reinterpret_cast<unsigned long long&>(d))
        : "l"(reinterpret_cast<unsigned long long&>(a)),
          "l"(reinterpret_cast<unsigned long long&>(b)),
          "l"(reinterpret_cast<unsigned long long&>(c)));
    return d;
}

__device__ __forceinline__ uint32_t smem_u32(const void* p) {
    uint32_t a;
    asm("{ .reg .u64 t; cvta.to.shared.u64 t, %1; cvt.u32.u64 %0, t; }" : "=r"(a) : "l"(p));
    return a;
}
#define SW128(x) ((x) ^ (((x) >> 3) & 0x70))

#define LDSM_X4(r0, r1, r2, r3, addr) \
    asm volatile("ldmatrix.sync.aligned.m8n8.x4.shared.b16 {%0,%1,%2,%3}, [%4];" \
        : "=r"(r0), "=r"(r1), "=r"(r2), "=r"(r3) : "r"(addr))

#define MMA16816(d, a, b) \
    asm volatile("mma.sync.aligned.m16n8k16.row.col.f32.f16.f16.f32 " \
        "{%0,%1,%2,%3}, {%4,%5,%6,%7}, {%8,%9}, {%0,%1,%2,%3};" \
        : "+f"(d[0]), "+f"(d[1]), "+f"(d[2]), "+f"(d[3]) \
        : "r"(a[0]), "r"(a[1]), "r"(a[2]), "r"(a[3]), "r"(b[0]), "r"(b[1]))

#define CP_ASYNC16(dst, src) \
    asm volatile("cp.async.cg.shared.global [%0], [%1], 16;" :: "r"(dst), "l"(src) : "memory")
#define CP_COMMIT() asm volatile("cp.async.commit_group;" ::: "memory")
#define CP_WAIT1()  asm volatile("cp.async.wait_group 1;" ::: "memory")
#define CP_WAIT0()  asm volatile("cp.async.wait_group 0;" ::: "memory")

// ---------------- hi/lo fp16 split conversions ----------------
__global__ __launch_bounds__(256) void conv_a_kernel(const float* __restrict__ X) {
    if (blockIdx.x == 0 && threadIdx.x == 0) g_cnt = 0u;   // reset recurrence barrier
    size_t gtid = (size_t)blockIdx.x * 256 + threadIdx.x;
    int k4 = (int)(gtid & 127);
    size_t row = gtid >> 7;              // b*1024 + s
    int b = (int)(row >> 10), s = (int)(row & 1023);
    float4 x = *(const float4*)(X + row * 512 + k4 * 4);
    float xv[4] = { x.x, x.y, x.z, x.w };
    __half h[4], l[4];
#pragma unroll
    for (int i = 0; i < 4; i++) {
        h[i] = __float2half_rn(xv[i]);
        l[i] = __float2half_rn(xv[i] - __half2float(h[i]));
    }
    size_t m = (size_t)s * 64 + b;
    __half* base = g_a2 + m * K2_ + k4 * 4;
    __half2 h01 = __halves2half2(h[0], h[1]), h23 = __halves2half2(h[2], h[3]);
    __half2 l01 = __halves2half2(l[0], l[1]), l23 = __halves2half2(l[2], l[3]);
    *(__half2*)(base + 0) = h01;        *(__half2*)(base + 2) = h23;
    *(__half2*)(base + 512) = h01;      *(__half2*)(base + 514) = h23;
    *(__half2*)(base + 1024) = l01;     *(__half2*)(base + 1026) = l23;
}

__global__ __launch_bounds__(256) void conv_b_kernel(const float* __restrict__ Wi) {
    size_t gtid = (size_t)blockIdx.x * 256 + threadIdx.x;
    int k4 = (int)(gtid & 127);
    size_t n = gtid >> 7;
    float4 x = *(const float4*)(Wi + n * 512 + k4 * 4);
    float xv[4] = { x.x, x.y, x.z, x.w };
    __half h[4], l[4];
#pragma unroll
    for (int i = 0; i < 4; i++) {
        h[i] = __float2half_rn(xv[i]);
        l[i] = __float2half_rn(xv[i] - __half2float(h[i]));
    }
    __half* base = g_b2 + n * K2_ + k4 * 4;
    __half2 h01 = __halves2half2(h[0], h[1]), h23 = __halves2half2(h[2], h[3]);
    __half2 l01 = __halves2half2(l[0], l[1]), l23 = __halves2half2(l[2], l[3]);
    *(__half2*)(base + 0) = h01;        *(__half2*)(base + 2) = h23;
    *(__half2*)(base + 512) = l01;      *(__half2*)(base + 514) = l23;
    *(__half2*)(base + 1024) = h01;     *(__half2*)(base + 1026) = h23;
}

// ---------------- Phase 1: HMMA GEMM, tile M=128 N=128 K=1536 ----------------
#define SMEM_GEMM 67584

__global__ __launch_bounds__(256, 2) void gemm_hmma_kernel(const float* __restrict__ bi) {
    extern __shared__ char smp[];
    const uint32_t sb = smem_u32(smp);
    const int tid = threadIdx.x, wid = tid >> 5, lane = tid & 31;
    const int n0 = blockIdx.x * 128;
    const int bm = blockIdx.y;

    const __half* Abase = g_a2 + (size_t)bm * 128 * K2_;
    const __half* Bbase = g_b2 + (size_t)n0 * K2_;

    const int warp_m = (wid & 1) * 64 + (wid >> 2) * 32;
    const int warp_n = ((wid >> 1) & 1) * 64;

    float acc[2][8][4];
#pragma unroll
    for (int mt = 0; mt < 2; mt++)
#pragma unroll
        for (int nt = 0; nt < 8; nt++)
#pragma unroll
            for (int q = 0; q < 4; q++) acc[mt][nt][q] = 0.f;

    auto issue = [&](int c, int buf) {
        const int kc = c * 64;
#pragma unroll
        for (int i = 0; i < 4; i++) {
            int flat = i * 256 + tid, row = flat >> 3, c16 = flat & 7;
            uint32_t da = sb + buf * 16384 + SW128(row * 128 + c16 * 16);
            CP_ASYNC16(da, (const void*)(Abase + (size_t)row * K2_ + kc + c16 * 8));
        }
#pragma unroll
        for (int i = 0; i < 4; i++) {
            int flat = i * 256 + tid, row = flat >> 3, c16 = flat & 7;
            uint32_t db = sb + 32768 + buf * 16384 + SW128(row * 128 + c16 * 16);
            CP_ASYNC16(db, (const void*)(Bbase + (size_t)row * K2_ + kc + c16 * 8));
        }
        CP_COMMIT();
    };

    issue(0, 0);

    for (int c = 0; c < NCH_; c++) {
        const int buf = c & 1;
        if (c + 1 < NCH_) { issue(c + 1, buf ^ 1); CP_WAIT1(); }
        else              { CP_WAIT0(); }
        __syncthreads();

        const uint32_t Aoff = sb + buf * 16384;
        const uint32_t Boff = sb + 32768 + buf * 16384;
        const int arow = warp_m + (lane & 15);
        const int brow = warp_n + (lane & 7) + ((lane & 16) ? 8 : 0);
        const int akb  = (lane & 16) ? 16 : 0;
        const int bkb  = (lane & 8) ? 16 : 0;

#pragma unroll
        for (int ks = 0; ks < 4; ks++) {
            uint32_t a[2][4];
#pragma unroll
            for (int mt = 0; mt < 2; mt++)
                LDSM_X4(a[mt][0], a[mt][1], a[mt][2], a[mt][3],
                        Aoff + SW128((arow + mt * 16) * 128 + ks * 32 + akb));
            uint32_t b[8][2];
#pragma unroll
            for (int bt = 0; bt < 4; bt++) {
                uint32_t r0, r1, r2, r3;
                LDSM_X4(r0, r1, r2, r3,
                        Boff + SW128((brow + bt * 16) * 128 + ks * 32 + bkb));
                b[bt * 2][0] = r0; b[bt * 2][1] = r1;
                b[bt * 2 + 1][0] = r2; b[bt * 2 + 1][1] = r3;
            }
#pragma unroll
            for (int mt = 0; mt < 2; mt++)
#pragma unroll
                for (int nt = 0; nt < 8; nt++)
                    MMA16816(acc[mt][nt], a[mt], b[nt]);
        }
        __syncthreads();
    }

    float* st = (float*)smp;
#pragma unroll
    for (int mt = 0; mt < 2; mt++)
#pragma unroll
        for (int nt = 0; nt < 8; nt++) {
            const int m = warp_m + mt * 16 + (lane >> 2);
            const int n = warp_n + nt * 8 + 2 * (lane & 3);
            st[n * 132 + m]           = acc[mt][nt][0];
            st[(n + 1) * 132 + m]     = acc[mt][nt][1];
            st[n * 132 + m + 8]       = acc[mt][nt][2];
            st[(n + 1) * 132 + m + 8] = acc[mt][nt][3];
        }
    __syncthreads();

#pragma unroll 4
    for (int it = 0; it < 64; it++) {
        int flat = it * 256 + tid;
        int m = flat & 127, n = flat >> 7;
        float v = st[n * 132 + m] + __ldg(bi + n0 + n);
        g_gx[(size_t)(bm * 2 + (m >> 6)) * (G_ * B_) + (size_t)(n0 + n) * B_ + (m & 63)] = v;
    }
}

// ---------------- Phase 2: recurrence v3 ----------------
// 128 CTAs x 256 thr. Warp = kq (k-range 64), covers all 16 gate rows x 64 batches.
// smem: hs [512][64] fp32 (131072B) | ws [16][512] (32768B) | red [8][16][32] float2 (32768B)
#define SMEM_LSTM (131072 + 32768 + 32768)

__global__ __launch_bounds__(256, 1) void lstm_kernel(
    const float* __restrict__ Wh, const float* __restrict__ bh,
    float* __restrict__ out)
{
    extern __shared__ float sm[];
    float* hs  = sm;
    float* ws  = sm + H4_ * B_;
    float* red = ws + 16 * H4_;
    const uint32_t hs_u32 = smem_u32(hs);

    const int tid = threadIdx.x;
    const int wid = tid >> 5;      // kq 0..7
    const int p   = tid & 31;      // batch pair
    const int j0  = blockIdx.x * 4;

    for (int i = tid; i < 16 * H4_; i += 256) {
        int r = i >> 9, k = i & 511;
        int g = r >> 2, jjr = r & 3;
        ws[i] = Wh[((size_t)(g * H4_ + j0 + jjr)) * H4_ + k];
    }
    for (int i = tid; i < H4_ * B_; i += 256) hs[i] = 0.f;

    const int jj = (tid >> 5) & 3;      // pointwise col (valid tid<128)
    float bb4[4];
    if (tid < 128) {
#pragma unroll
        for (int g = 0; g < 4; g++) bb4[g] = bh[g * H4_ + j0 + jj];
    }
    __syncthreads();

    const float2* hs2 = (const float2*)hs;
    float2* red2 = (float2*)red;

    // prefetch gx(0)
    float2 gx[4];
    if (tid < 128) {
        const float2* gxp = (const float2*)g_gx;
#pragma unroll
        for (int g = 0; g < 4; g++)
            gx[g] = gxp[(g * H4_ + j0 + jj) * 32 + p];
    }

    float2 cst = make_float2(0.f, 0.f);
    const int kb = wid * 64;

    for (int t = 0; t < S_; t++) {
        // ---- GEMV: 16 gate rows x 64 k x 64 b per warp ----
        float2 acc[16];
#pragma unroll
        for (int r = 0; r < 16; r++) acc[r] = make_float2(0.f, 0.f);
#pragma unroll 4
        for (int kc = 0; kc < 64; kc += 4) {
            const int kk = kb + kc;
            float2 h0 = hs2[(kk + 0) * 32 + p];
            float2 h1 = hs2[(kk + 1) * 32 + p];
            float2 h2 = hs2[(kk + 2) * 32 + p];
            float2 h3 = hs2[(kk + 3) * 32 + p];
#pragma unroll
            for (int r = 0; r < 16; r++) {
                float4 wv = *(const float4*)&ws[r * H4_ + kk];
                acc[r] = ffma2(make_float2(wv.x, wv.x), h0, acc[r]);
                acc[r] = ffma2(make_float2(wv.y, wv.y), h1, acc[r]);
                acc[r] = ffma2(make_float2(wv.z, wv.z), h2, acc[r]);
                acc[r] = ffma2(make_float2(wv.w, wv.w), h3, acc[r]);
            }
        }
#pragma unroll
        for (int r = 0; r < 16; r++)
            red2[(wid * 16 + r) * 32 + p] = acc[r];
        __syncthreads();

        // ---- fused reduce + pointwise (128 threads) ----
        float hsv0 = 0.f, hsv1 = 0.f, csv0 = 0.f, csv1 = 0.f;
        if (tid < 128) {
            float2 pre[4];
#pragma unroll
            for (int g = 0; g < 4; g++) {
                const int r = g * 4 + jj;
                float2 s = make_float2(gx[g].x + bb4[g], gx[g].y + bb4[g]);
#pragma unroll
                for (int w = 0; w < 8; w++) {
                    float2 v = red2[(w * 16 + r) * 32 + p];
                    s.x += v.x; s.y += v.y;
                }
                pre[g] = s;
            }
            {
                float iv = 1.f / (1.f + __expf(-pre[0].x));
                float fv = 1.f / (1.f + __expf(-pre[1].x));
                float gv = tanhf(pre[2].x);
                float ov = 1.f / (1.f + __expf(-pre[3].x));
                float c = fv * cst.x + iv * gv;
                cst.x = c; csv0 = c; hsv0 = ov * tanhf(c);
            }
            {
                float iv = 1.f / (1.f + __expf(-pre[0].y));
                float fv = 1.f / (1.f + __expf(-pre[1].y));
                float gv = tanhf(pre[2].y);
                float ov = 1.f / (1.f + __expf(-pre[3].y));
                float c = fv * cst.y + iv * gv;
                cst.y = c; csv1 = c; hsv1 = ov * tanhf(c);
            }
            float* hnext = g_hbuf[(t + 1) & 1];
            *(float2*)&hnext[(j0 + jj) * B_ + 2 * p] = make_float2(hsv0, hsv1);
            if (t == S_ - 1) {
                const int b0 = 2 * p, j = j0 + jj;
                out[(size_t)B_ * S_ * H4_ + (size_t)b0 * H4_ + j] = hsv0;
                out[(size_t)B_ * S_ * H4_ + (size_t)(b0 + 1) * H4_ + j] = hsv1;
                out[(size_t)B_ * S_ * H4_ + (size_t)B_ * H4_ + (size_t)b0 * H4_ + j] = csv0;
                out[(size_t)B_ * S_ * H4_ + (size_t)B_ * H4_ + (size_t)(b0 + 1) * H4_ + j] = csv1;
            }
        }
        __syncthreads();

        if (t < S_ - 1) {
            // arrive: release-red, no return
            if (tid == 0)
                asm volatile("red.release.gpu.global.add.u32 [%0], %1;"
                             :: "l"(&g_cnt), "r"(1u) : "memory");
            // poll: all threads, acquire
            const unsigned tgt = (unsigned)(t + 1) * NCTA2;
            unsigned v;
            do {
                asm volatile("ld.acquire.gpu.global.u32 %0, [%1];"
                             : "=r"(v) : "l"(&g_cnt) : "memory");
            } while (v < tgt);

            // cp.async: copy h(t+1) into hs
            {
                const char* src = (const char*)g_hbuf[(t + 1) & 1];
#pragma unroll 8
                for (int i = 0; i < 32; i++) {
                    const int off = (i * 256 + tid) * 16;
                    CP_ASYNC16(hs_u32 + off, src + off);
                }
                CP_COMMIT();
            }
            // overlap: out stores for t, gx prefetch for t+1
            if (tid < 128) {
                const int b0 = 2 * p, j = j0 + jj;
                out[((size_t)b0 * S_ + t) * H4_ + j] = hsv0;
                out[((size_t)(b0 + 1) * S_ + t) * H4_ + j] = hsv1;
                const float2* gxp = (const float2*)(g_gx + (size_t)(t + 1) * (G_ * B_));
#pragma unroll
                for (int g = 0; g < 4; g++)
                    gx[g] = gxp[(g * H4_ + j0 + jj) * 32 + p];
            }
            CP_WAIT0();
            __syncthreads();
        } else {
            if (tid < 128) {
                const int b0 = 2 * p, j = j0 + jj;
                out[((size_t)b0 * S_ + t) * H4_ + j] = hsv0;
                out[((size_t)(b0 + 1) * S_ + t) * H4_ + j] = hsv1;
            }
        }
    }
}

extern "C" void kernel_launch(void* const* d_in, const int* in_sizes, int n_in,
                              void* d_out, int out_size) {
    const float* X  = (const float*)d_in[0];
    const float* Wi = (const float*)d_in[1];
    const float* Wh = (const float*)d_in[2];
    const float* bi = (const float*)d_in[3];
    const float* bh = (const float*)d_in[4];
    float* out = (float*)d_out;

    cudaFuncSetAttribute(gemm_hmma_kernel, cudaFuncAttributeMaxDynamicSharedMemorySize, SMEM_GEMM);
    cudaFuncSetAttribute(lstm_kernel, cudaFuncAttributeMaxDynamicSharedMemorySize, SMEM_LSTM);

    conv_a_kernel<<<32768, 256>>>(X);
    conv_b_kernel<<<1024, 256>>>(Wi);
    gemm_hmma_kernel<<<dim3(16, 512), 256, SMEM_GEMM>>>(bi);
    lstm_kernel<<<NCTA2, 256, SMEM_LSTM>>>(Wh, bh, out);
}

// round 14
// speedup vs baseline: 1.7077x; 1.0401x over previous
#include <cuda_runtime.h>
#include <cuda_fp16.h>
#include <cstdint>

#define B_   64
#define S_   1024
#define IN_  512
#define H4_  512
#define G_   2048
#define NCTA2 64
#define K2_  1536
#define NCH_ 24

__device__ float    g_gx[(size_t)S_ * G_ * B_];   // [s][n][b]
__device__ __half   g_a2[(size_t)S_ * B_ * K2_];  // [m=s*64+b][k']
__device__ __half   g_b2[(size_t)G_ * K2_];       // [n][k']
__device__ __half   g_w2[(size_t)G_ * 1024];      // Wh hi|lo  [row][k']
__device__ __half   g_h2[2][64 * 1024];           // h hi|lo   [b][k']
__device__ unsigned g_cnt;

__device__ __forceinline__ uint32_t smem_u32(const void* p) {
    uint32_t a;
    asm("{ .reg .u64 t; cvta.to.shared.u64 t, %1; cvt.u32.u64 %0, t; }" : "=r"(a) : "l"(p));
    return a;
}
#define SW128(x) ((x) ^ (((x) >> 3) & 0x70))

#define LDSM_X4(r0, r1, r2, r3, addr) \
    asm volatile("ldmatrix.sync.aligned.m8n8.x4.shared.b16 {%0,%1,%2,%3}, [%4];" \
        : "=r"(r0), "=r"(r1), "=r"(r2), "=r"(r3) : "r"(addr))

#define MMA16816(d, a, b) \
    asm volatile("mma.sync.aligned.m16n8k16.row.col.f32.f16.f16.f32 " \
        "{%0,%1,%2,%3}, {%4,%5,%6,%7}, {%8,%9}, {%0,%1,%2,%3};" \
        : "+f"(d[0]), "+f"(d[1]), "+f"(d[2]), "+f"(d[3]) \
        : "r"(a[0]), "r"(a[1]), "r"(a[2]), "r"(a[3]), "r"(b[0]), "r"(b[1]))

#define CP_ASYNC16(dst, src) \
    asm volatile("cp.async.cg.shared.global [%0], [%1], 16;" :: "r"(dst), "l"(src) : "memory")
#define CP_COMMIT() asm volatile("cp.async.commit_group;" ::: "memory")
#define CP_WAIT1()  asm volatile("cp.async.wait_group 1;" ::: "memory")
#define CP_WAIT0()  asm volatile("cp.async.wait_group 0;" ::: "memory")

// ---------------- conversions ----------------
__global__ __launch_bounds__(256) void conv_a_kernel(const float* __restrict__ X) {
    size_t gtid = (size_t)blockIdx.x * 256 + threadIdx.x;
    if (gtid == 0) g_cnt = 0u;
    if (gtid < 8192) ((float4*)g_h2[0])[gtid] = make_float4(0.f, 0.f, 0.f, 0.f);
    int k4 = (int)(gtid & 127);
    size_t row = gtid >> 7;              // b*1024 + s
    int b = (int)(row >> 10), s = (int)(row & 1023);
    float4 x = *(const float4*)(X + row * 512 + k4 * 4);
    float xv[4] = { x.x, x.y, x.z, x.w };
    __half h[4], l[4];
#pragma unroll
    for (int i = 0; i < 4; i++) {
        h[i] = __float2half_rn(xv[i]);
        l[i] = __float2half_rn(xv[i] - __half2float(h[i]));
    }
    size_t m = (size_t)s * 64 + b;
    __half* base = g_a2 + m * K2_ + k4 * 4;
    __half2 h01 = __halves2half2(h[0], h[1]), h23 = __halves2half2(h[2], h[3]);
    __half2 l01 = __halves2half2(l[0], l[1]), l23 = __halves2half2(l[2], l[3]);
    *(__half2*)(base + 0) = h01;        *(__half2*)(base + 2) = h23;
    *(__half2*)(base + 512) = h01;      *(__half2*)(base + 514) = h23;
    *(__half2*)(base + 1024) = l01;     *(__half2*)(base + 1026) = l23;
}

__global__ __launch_bounds__(256) void conv_b_kernel(const float* __restrict__ Wi) {
    size_t gtid = (size_t)blockIdx.x * 256 + threadIdx.x;
    int k4 = (int)(gtid & 127);
    size_t n = gtid >> 7;
    float4 x = *(const float4*)(Wi + n * 512 + k4 * 4);
    float xv[4] = { x.x, x.y, x.z, x.w };
    __half h[4], l[4];
#pragma unroll
    for (int i = 0; i < 4; i++) {
        h[i] = __float2half_rn(xv[i]);
        l[i] = __float2half_rn(xv[i] - __half2float(h[i]));
    }
    __half* base = g_b2 + n * K2_ + k4 * 4;
    __half2 h01 = __halves2half2(h[0], h[1]), h23 = __halves2half2(h[2], h[3]);
    __half2 l01 = __halves2half2(l[0], l[1]), l23 = __halves2half2(l[2], l[3]);
    *(__half2*)(base + 0) = h01;        *(__half2*)(base + 2) = h23;
    *(__half2*)(base + 512) = l01;      *(__half2*)(base + 514) = l23;
    *(__half2*)(base + 1024) = h01;     *(__half2*)(base + 1026) = h23;
}

__global__ __launch_bounds__(256) void conv_w_kernel(const float* __restrict__ Wh) {
    size_t gtid = (size_t)blockIdx.x * 256 + threadIdx.x;   // 262144
    int k4 = (int)(gtid & 127);
    size_t n = gtid >> 7;                // gate row 0..2047
    float4 x = *(const float4*)(Wh + n * 512 + k4 * 4);
    float xv[4] = { x.x, x.y, x.z, x.w };
    __half h[4], l[4];
#pragma unroll
    for (int i = 0; i < 4; i++) {
        h[i] = __float2half_rn(xv[i]);
        l[i] = __float2half_rn(xv[i] - __half2float(h[i]));
    }
    __half* base = g_w2 + n * 1024 + k4 * 4;
    *(__half2*)(base + 0)   = __halves2half2(h[0], h[1]);
    *(__half2*)(base + 2)   = __halves2half2(h[2], h[3]);
    *(__half2*)(base + 512) = __halves2half2(l[0], l[1]);
    *(__half2*)(base + 514) = __halves2half2(l[2], l[3]);
}

// ---------------- Phase 1: HMMA GEMM, tile M=128 N=128 K=1536 ----------------
#define SMEM_GEMM 67584

__global__ __launch_bounds__(256, 2) void gemm_hmma_kernel(const float* __restrict__ bi) {
    extern __shared__ char smp[];
    const uint32_t sb = smem_u32(smp);
    const int tid = threadIdx.x, wid = tid >> 5, lane = tid & 31;
    const int n0 = blockIdx.x * 128;
    const int bm = blockIdx.y;

    const __half* Abase = g_a2 + (size_t)bm * 128 * K2_;
    const __half* Bbase = g_b2 + (size_t)n0 * K2_;

    const int warp_m = (wid & 1) * 64 + (wid >> 2) * 32;
    const int warp_n = ((wid >> 1) & 1) * 64;

    float acc[2][8][4];
#pragma unroll
    for (int mt = 0; mt < 2; mt++)
#pragma unroll
        for (int nt = 0; nt < 8; nt++)
#pragma unroll
            for (int q = 0; q < 4; q++) acc[mt][nt][q] = 0.f;

    auto issue = [&](int c, int buf) {
        const int kc = c * 64;
#pragma unroll
        for (int i = 0; i < 4; i++) {
            int flat = i * 256 + tid, row = flat >> 3, c16 = flat & 7;
            uint32_t da = sb + buf * 16384 + SW128(row * 128 + c16 * 16);
            CP_ASYNC16(da, (const void*)(Abase + (size_t)row * K2_ + kc + c16 * 8));
        }
#pragma unroll
        for (int i = 0; i < 4; i++) {
            int flat = i * 256 + tid, row = flat >> 3, c16 = flat & 7;
            uint32_t db = sb + 32768 + buf * 16384 + SW128(row * 128 + c16 * 16);
            CP_ASYNC16(db, (const void*)(Bbase + (size_t)row * K2_ + kc + c16 * 8));
        }
        CP_COMMIT();
    };

    issue(0, 0);

    for (int c = 0; c < NCH_; c++) {
        const int buf = c & 1;
        if (c + 1 < NCH_) { issue(c + 1, buf ^ 1); CP_WAIT1(); }
        else              { CP_WAIT0(); }
        __syncthreads();

        const uint32_t Aoff = sb + buf * 16384;
        const uint32_t Boff = sb + 32768 + buf * 16384;
        const int arow = warp_m + (lane & 15);
        const int brow = warp_n + (lane & 7) + ((lane & 16) ? 8 : 0);
        const int akb  = (lane & 16) ? 16 : 0;
        const int bkb  = (lane & 8) ? 16 : 0;

#pragma unroll
        for (int ks = 0; ks < 4; ks++) {
            uint32_t a[2][4];
#pragma unroll
            for (int mt = 0; mt < 2; mt++)
                LDSM_X4(a[mt][0], a[mt][1], a[mt][2], a[mt][3],
                        Aoff + SW128((arow + mt * 16) * 128 + ks * 32 + akb));
            uint32_t b[8][2];
#pragma unroll
            for (int bt = 0; bt < 4; bt++) {
                uint32_t r0, r1, r2, r3;
                LDSM_X4(r0, r1, r2, r3,
                        Boff + SW128((brow + bt * 16) * 128 + ks * 32 + bkb));
                b[bt * 2][0] = r0; b[bt * 2][1] = r1;
                b[bt * 2 + 1][0] = r2; b[bt * 2 + 1][1] = r3;
            }
#pragma unroll
            for (int mt = 0; mt < 2; mt++)
#pragma unroll
                for (int nt = 0; nt < 8; nt++)
                    MMA16816(acc[mt][nt], a[mt], b[nt]);
        }
        __syncthreads();
    }

    float* st = (float*)smp;
#pragma unroll
    for (int mt = 0; mt < 2; mt++)
#pragma unroll
        for (int nt = 0; nt < 8; nt++) {
            const int m = warp_m + mt * 16 + (lane >> 2);
            const int n = warp_n + nt * 8 + 2 * (lane & 3);
            st[n * 132 + m]           = acc[mt][nt][0];
            st[(n + 1) * 132 + m]     = acc[mt][nt][1];
            st[n * 132 + m + 8]       = acc[mt][nt][2];
            st[(n + 1) * 132 + m + 8] = acc[mt][nt][3];
        }
    __syncthreads();

#pragma unroll 4
    for (int it = 0; it < 64; it++) {
        int flat = it * 256 + tid;
        int m = flat & 127, n = flat >> 7;
        float v = st[n * 132 + m] + __ldg(bi + n0 + n);
        g_gx[(size_t)(bm * 2 + (m >> 6)) * (G_ * B_) + (size_t)(n0 + n) * B_ + (m & 63)] = v;
    }
}

// ---------------- Phase 2: recurrence v4 (HMMA GEMV) ----------------
// 64 CTAs x 256 thr; CTA owns 8 states (j0=cta*8) = 32 gate rows (local n = jl*4+g).
// smem: A h-tile [64][1024]f16 swz (131072) | W [32][1024]f16 swz (65536)
//       | gates [32][66]f32 (8448) | gx 2x[32][64]f32 (16384) | hstage 1024 f16 (2048)
#define A_OFF  0
#define W_OFF  131072
#define G_OFF  196608
#define GX_OFF 205056
#define HS_OFF 221440
#define SMEM_LSTM 223488

__global__ __launch_bounds__(256, 1) void lstm_kernel(
    const float* __restrict__ bh, float* __restrict__ out)
{
    extern __shared__ char smp[];
    const uint32_t sb = smem_u32(smp);
    float* gates_s = (float*)(smp + G_OFF);
    float* gx_s    = (float*)(smp + GX_OFF);
    __half* hst    = (__half*)(smp + HS_OFF);

    const int tid = threadIdx.x, wid = tid >> 5, lane = tid & 31;
    const int j0 = blockIdx.x * 8;

    // preload: W slice, h(0), gx(0)
    {
#pragma unroll
        for (int i = 0; i < 16; i++) {
            int q = i * 256 + tid;             // 4096 chunks
            int lrow = q >> 7, c16 = q & 127;
            int g = lrow & 3, jl = lrow >> 2;
            CP_ASYNC16(sb + W_OFF + lrow * 2048 + ((c16 ^ (lrow & 7)) << 4),
                       (const void*)(g_w2 + (size_t)(g * 512 + j0 + jl) * 1024 + c16 * 8));
        }
#pragma unroll
        for (int i = 0; i < 32; i++) {
            int q = i * 256 + tid;             // 8192 chunks
            int r = q >> 7, c16 = q & 127;
            CP_ASYNC16(sb + A_OFF + r * 2048 + ((c16 ^ (r & 7)) << 4),
                       (const void*)(g_h2[0] + (size_t)r * 1024 + c16 * 8));
        }
#pragma unroll
        for (int i = 0; i < 2; i++) {
            int q = i * 256 + tid;             // 512 chunks
            int n = q >> 4, c = q & 15;
            int g = n & 3, jl = n >> 2;
            CP_ASYNC16(sb + GX_OFF + (n * 64 + c * 4) * 4,
                       (const void*)(g_gx + (size_t)(g * 512 + j0 + jl) * 64 + c * 4));
        }
        CP_COMMIT();
        CP_WAIT0();
    }
    __syncthreads();

    const int pjl = tid >> 6;    // 0..3
    const int pb  = tid & 63;
    float bias0[4], bias1[4];
#pragma unroll
    for (int g = 0; g < 4; g++) {
        bias0[g] = bh[g * 512 + j0 + pjl];
        bias1[g] = bh[g * 512 + j0 + pjl + 4];
    }
    float cs0 = 0.f, cs1 = 0.f;

    // mma lane setup: warp = (mt 0..3, ng 0..1)
    const int mt = wid & 3, ng = wid >> 2;
    const int arow = mt * 16 + (lane & 15);
    const int abit = (lane >> 4) & 1;
    const uint32_t abase = sb + A_OFF + arow * 2048;
    const uint32_t aph = (uint32_t)(arow & 7);
    const int brow = ng * 16 + (lane & 7) + ((lane & 16) ? 8 : 0);
    const int bbit = (lane >> 3) & 1;
    const uint32_t bbase = sb + W_OFF + brow * 2048;
    const uint32_t bph = (uint32_t)(brow & 7);

    for (int t = 0; t < S_; t++) {
        float acc0[4] = {0.f, 0.f, 0.f, 0.f}, acc1[4] = {0.f, 0.f, 0.f, 0.f};
        // pass 1: A = [h_hi | h_lo] (k' 0..1023), B = w_hi (cycled twice)
#pragma unroll 4
        for (int ks = 0; ks < 64; ks++) {
            uint32_t ca = (uint32_t)(ks * 2 + abit);
            uint32_t cb = (uint32_t)(((ks * 2) & 63) + bbit);
            uint32_t a0, a1, a2, a3, b0, b1, b2, b3;
            LDSM_X4(a0, a1, a2, a3, abase + ((ca ^ aph) << 4));
            LDSM_X4(b0, b1, b2, b3, bbase + ((cb ^ bph) << 4));
            uint32_t av[4] = {a0, a1, a2, a3};
            uint32_t bv0[2] = {b0, b1}, bv1[2] = {b2, b3};
            MMA16816(acc0, av, bv0);
            MMA16816(acc1, av, bv1);
        }
        // pass 2: A = h_hi (k' 0..511), B = w_lo
#pragma unroll 4
        for (int ks = 0; ks < 32; ks++) {
            uint32_t ca = (uint32_t)(ks * 2 + abit);
            uint32_t cb = (uint32_t)(64 + ks * 2 + bbit);
            uint32_t a0, a1, a2, a3, b0, b1, b2, b3;
            LDSM_X4(a0, a1, a2, a3, abase + ((ca ^ aph) << 4));
            LDSM_X4(b0, b1, b2, b3, bbase + ((cb ^ bph) << 4));
            uint32_t av[4] = {a0, a1, a2, a3};
            uint32_t bv0[2] = {b0, b1}, bv1[2] = {b2, b3};
            MMA16816(acc0, av, bv0);
            MMA16816(acc1, av, bv1);
        }

        // frags -> gates_s[n][m]
        {
            const int fm = mt * 16 + (lane >> 2);
            const int fn = ng * 16 + 2 * (lane & 3);
            gates_s[fn * 66 + fm]           = acc0[0];
            gates_s[(fn + 1) * 66 + fm]     = acc0[1];
            gates_s[fn * 66 + fm + 8]       = acc0[2];
            gates_s[(fn + 1) * 66 + fm + 8] = acc0[3];
            gates_s[(fn + 8) * 66 + fm]           = acc1[0];
            gates_s[(fn + 9) * 66 + fm]           = acc1[1];
            gates_s[(fn + 8) * 66 + fm + 8]       = acc1[2];
            gates_s[(fn + 9) * 66 + fm + 8]       = acc1[3];
        }
        if (t > 0) CP_WAIT0();     // gx(t) group
        __syncthreads();

        // fused pointwise: thread = (pjl, pb), pairs j = j0+pjl and j0+pjl+4
        const float* gxb = gx_s + (t & 1) * 2048;
        float pre0[4], pre1[4];
#pragma unroll
        for (int g = 0; g < 4; g++) {
            int n0i = pjl * 4 + g, n1i = (pjl + 4) * 4 + g;
            pre0[g] = gates_s[n0i * 66 + pb] + gxb[n0i * 64 + pb] + bias0[g];
            pre1[g] = gates_s[n1i * 66 + pb] + gxb[n1i * 64 + pb] + bias1[g];
        }
        float h0, h1;
        {
            float iv = 1.f / (1.f + __expf(-pre0[0]));
            float fv = 1.f / (1.f + __expf(-pre0[1]));
            float gv = tanhf(pre0[2]);
            float ov = 1.f / (1.f + __expf(-pre0[3]));
            cs0 = fv * cs0 + iv * gv;
            h0 = ov * tanhf(cs0);
        }
        {
            float iv = 1.f / (1.f + __expf(-pre1[0]));
            float fv = 1.f / (1.f + __expf(-pre1[1]));
            float gv = tanhf(pre1[2]);
            float ov = 1.f / (1.f + __expf(-pre1[3]));
            cs1 = fv * cs1 + iv * gv;
            h1 = ov * tanhf(cs1);
        }
        out[((size_t)pb * S_ + t) * H4_ + j0 + pjl]     = h0;
        out[((size_t)pb * S_ + t) * H4_ + j0 + pjl + 4] = h1;

        if (t == S_ - 1) {
            const size_t ob = (size_t)B_ * S_ * H4_;
            out[ob + (size_t)pb * H4_ + j0 + pjl]     = h0;
            out[ob + (size_t)pb * H4_ + j0 + pjl + 4] = h1;
            out[ob + (size_t)B_ * H4_ + (size_t)pb * H4_ + j0 + pjl]     = cs0;
            out[ob + (size_t)B_ * H4_ + (size_t)pb * H4_ + j0 + pjl + 4] = cs1;
        } else {
            __half hh0 = __float2half_rn(h0);
            __half hl0 = __float2half_rn(h0 - __half2float(hh0));
            __half hh1 = __float2half_rn(h1);
            __half hl1 = __float2half_rn(h1 - __half2float(hh1));
            hst[pb * 8 + pjl]           = hh0;
            hst[pb * 8 + pjl + 4]       = hh1;
            hst[512 + pb * 8 + pjl]     = hl0;
            hst[512 + pb * 8 + pjl + 4] = hl1;
        }
        __syncthreads();

        if (t < S_ - 1) {
            const int buf = (t + 1) & 1;
            if (tid < 64) {
                float4 v = *(float4*)(hst + tid * 8);
                *(float4*)(g_h2[buf] + (size_t)tid * 1024 + j0) = v;
            } else if (tid < 128) {
                int b = tid - 64;
                float4 v = *(float4*)(hst + 512 + b * 8);
                *(float4*)(g_h2[buf] + (size_t)b * 1024 + 512 + j0) = v;
            }
            __syncthreads();
            if (tid == 0)
                asm volatile("red.release.gpu.global.add.u32 [%0], %1;"
                             :: "l"(&g_cnt), "r"(1u) : "memory");
            const unsigned tgt = (unsigned)(t + 1) * NCTA2;
            unsigned v;
            do {
                asm volatile("ld.acquire.gpu.global.u32 %0, [%1];"
                             : "=r"(v) : "l"(&g_cnt) : "memory");
            } while (v < tgt);

            // h(t+1) -> A tile
#pragma unroll
            for (int i = 0; i < 32; i++) {
                int q = i * 256 + tid;
                int r = q >> 7, c16 = q & 127;
                CP_ASYNC16(sb + A_OFF + r * 2048 + ((c16 ^ (r & 7)) << 4),
                           (const void*)(g_h2[buf] + (size_t)r * 1024 + c16 * 8));
            }
            CP_COMMIT();
            // gx(t+1)
#pragma unroll
            for (int i = 0; i < 2; i++) {
                int q = i * 256 + tid;
                int n = q >> 4, c = q & 15;
                int g = n & 3, jl = n >> 2;
                CP_ASYNC16(sb + GX_OFF + (buf * 2048 + n * 64 + c * 4) * 4,
                           (const void*)(g_gx + (size_t)(t + 1) * (G_ * B_)
                                         + (size_t)(g * 512 + j0 + jl) * 64 + c * 4));
            }
            CP_COMMIT();
            CP_WAIT1();       // h done (gx may stay pending)
            __syncthreads();
        }
    }
}

extern "C" void kernel_launch(void* const* d_in, const int* in_sizes, int n_in,
                              void* d_out, int out_size) {
    const float* X  = (const float*)d_in[0];
    const float* Wi = (const float*)d_in[1];
    const float* Wh = (const float*)d_in[2];
    const float* bi = (const float*)d_in[3];
    const float* bh = (const float*)d_in[4];
    float* out = (float*)d_out;

    cudaFuncSetAttribute(gemm_hmma_kernel, cudaFuncAttributeMaxDynamicSharedMemorySize, SMEM_GEMM);
    cudaFuncSetAttribute(lstm_kernel, cudaFuncAttributeMaxDynamicSharedMemorySize, SMEM_LSTM);

    conv_a_kernel<<<32768, 256>>>(X);
    conv_b_kernel<<<1024, 256>>>(Wi);
    conv_w_kernel<<<1024, 256>>>(Wh);
    gemm_hmma_kernel<<<dim3(16, 512), 256, SMEM_GEMM>>>(bi);
    lstm_kernel<<<NCTA2, 256, SMEM_LSTM>>>(bh, out);
}

// round 15
// speedup vs baseline: 1.9727x; 1.1551x over previous
#include <cuda_runtime.h>
#include <cuda_fp16.h>
#include <cstdint>

#define B_   64
#define S_   1024
#define IN_  512
#define H4_  512
#define G_   2048
#define NCTA2 128
#define K2_  1536
#define NCH_ 24

__device__ float    g_gx[(size_t)S_ * G_ * B_];   // [s][n][b]
__device__ __half   g_a2[(size_t)S_ * B_ * K2_];  // [m=s*64+b][k']
__device__ __half   g_b2[(size_t)G_ * K2_];       // [n][k']
__device__ __half   g_w2[(size_t)G_ * 1024];      // Wh hi|lo  [row][k']
__device__ __half   g_h2[2][64 * 1024];           // h hi|lo   [b][k']
__device__ unsigned g_cnt;

__device__ __forceinline__ uint32_t smem_u32(const void* p) {
    uint32_t a;
    asm("{ .reg .u64 t; cvta.to.shared.u64 t, %1; cvt.u32.u64 %0, t; }" : "=r"(a) : "l"(p));
    return a;
}
#define SW128(x) ((x) ^ (((x) >> 3) & 0x70))

#define LDSM_X4(r0, r1, r2, r3, addr) \
    asm volatile("ldmatrix.sync.aligned.m8n8.x4.shared.b16 {%0,%1,%2,%3}, [%4];" \
        : "=r"(r0), "=r"(r1), "=r"(r2), "=r"(r3) : "r"(addr))

#define MMA16816(d, a, b) \
    asm volatile("mma.sync.aligned.m16n8k16.row.col.f32.f16.f16.f32 " \
        "{%0,%1,%2,%3}, {%4,%5,%6,%7}, {%8,%9}, {%0,%1,%2,%3};" \
        : "+f"(d[0]), "+f"(d[1]), "+f"(d[2]), "+f"(d[3]) \
        : "r"(a[0]), "r"(a[1]), "r"(a[2]), "r"(a[3]), "r"(b[0]), "r"(b[1]))

#define CP_ASYNC16(dst, src) \
    asm volatile("cp.async.cg.shared.global [%0], [%1], 16;" :: "r"(dst), "l"(src) : "memory")
#define CP_COMMIT() asm volatile("cp.async.commit_group;" ::: "memory")
#define CP_WAIT1()  asm volatile("cp.async.wait_group 1;" ::: "memory")
#define CP_WAIT0()  asm volatile("cp.async.wait_group 0;" ::: "memory")

// ---------------- conversions ----------------
__global__ __launch_bounds__(256) void conv_a_kernel(const float* __restrict__ X) {
    size_t gtid = (size_t)blockIdx.x * 256 + threadIdx.x;
    if (gtid == 0) g_cnt = 0u;
    if (gtid < 8192) ((float4*)g_h2[0])[gtid] = make_float4(0.f, 0.f, 0.f, 0.f);
    int k4 = (int)(gtid & 127);
    size_t row = gtid >> 7;              // b*1024 + s
    int b = (int)(row >> 10), s = (int)(row & 1023);
    float4 x = *(const float4*)(X + row * 512 + k4 * 4);
    float xv[4] = { x.x, x.y, x.z, x.w };
    __half h[4], l[4];
#pragma unroll
    for (int i = 0; i < 4; i++) {
        h[i] = __float2half_rn(xv[i]);
        l[i] = __float2half_rn(xv[i] - __half2float(h[i]));
    }
    size_t m = (size_t)s * 64 + b;
    __half* base = g_a2 + m * K2_ + k4 * 4;
    __half2 h01 = __halves2half2(h[0], h[1]), h23 = __halves2half2(h[2], h[3]);
    __half2 l01 = __halves2half2(l[0], l[1]), l23 = __halves2half2(l[2], l[3]);
    *(__half2*)(base + 0) = h01;        *(__half2*)(base + 2) = h23;
    *(__half2*)(base + 512) = h01;      *(__half2*)(base + 514) = h23;
    *(__half2*)(base + 1024) = l01;     *(__half2*)(base + 1026) = l23;
}

__global__ __launch_bounds__(256) void conv_b_kernel(const float* __restrict__ Wi) {
    size_t gtid = (size_t)blockIdx.x * 256 + threadIdx.x;
    int k4 = (int)(gtid & 127);
    size_t n = gtid >> 7;
    float4 x = *(const float4*)(Wi + n * 512 + k4 * 4);
    float xv[4] = { x.x, x.y, x.z, x.w };
    __half h[4], l[4];
#pragma unroll
    for (int i = 0; i < 4; i++) {
        h[i] = __float2half_rn(xv[i]);
        l[i] = __float2half_rn(xv[i] - __half2float(h[i]));
    }
    __half* base = g_b2 + n * K2_ + k4 * 4;
    *(__half2*)(base + 0)    = __halves2half2(h[0], h[1]);
    *(__half2*)(base + 2)    = __halves2half2(h[2], h[3]);
    *(__half2*)(base + 512)  = __halves2half2(l[0], l[1]);
    *(__half2*)(base + 514)  = __halves2half2(l[2], l[3]);
    *(__half2*)(base + 1024) = __halves2half2(h[0], h[1]);
    *(__half2*)(base + 1026) = __halves2half2(h[2], h[3]);
}

__global__ __launch_bounds__(256) void conv_w_kernel(const float* __restrict__ Wh) {
    size_t gtid = (size_t)blockIdx.x * 256 + threadIdx.x;   // 262144
    int k4 = (int)(gtid & 127);
    size_t n = gtid >> 7;                // gate row 0..2047
    float4 x = *(const float4*)(Wh + n * 512 + k4 * 4);
    float xv[4] = { x.x, x.y, x.z, x.w };
    __half h[4], l[4];
#pragma unroll
    for (int i = 0; i < 4; i++) {
        h[i] = __float2half_rn(xv[i]);
        l[i] = __float2half_rn(xv[i] - __half2float(h[i]));
    }
    __half* base = g_w2 + n * 1024 + k4 * 4;
    *(__half2*)(base + 0)   = __halves2half2(h[0], h[1]);
    *(__half2*)(base + 2)   = __halves2half2(h[2], h[3]);
    *(__half2*)(base + 512) = __halves2half2(l[0], l[1]);
    *(__half2*)(base + 514) = __halves2half2(l[2], l[3]);
}

// ---------------- Phase 1: HMMA GEMM, tile M=128 N=128 K=1536 ----------------
#define SMEM_GEMM 67584

__global__ __launch_bounds__(256, 2) void gemm_hmma_kernel(const float* __restrict__ bi) {
    extern __shared__ char smp[];
    const uint32_t sb = smem_u32(smp);
    const int tid = threadIdx.x, wid = tid >> 5, lane = tid & 31;
    const int n0 = blockIdx.x * 128;
    const int bm = blockIdx.y;

    const __half* Abase = g_a2 + (size_t)bm * 128 * K2_;
    const __half* Bbase = g_b2 + (size_t)n0 * K2_;

    const int warp_m = (wid & 1) * 64 + (wid >> 2) * 32;
    const int warp_n = ((wid >> 1) & 1) * 64;

    float acc[2][8][4];
#pragma unroll
    for (int mt = 0; mt < 2; mt++)
#pragma unroll
        for (int nt = 0; nt < 8; nt++)
#pragma unroll
            for (int q = 0; q < 4; q++) acc[mt][nt][q] = 0.f;

    auto issue = [&](int c, int buf) {
        const int kc = c * 64;
#pragma unroll
        for (int i = 0; i < 4; i++) {
            int flat = i * 256 + tid, row = flat >> 3, c16 = flat & 7;
            uint32_t da = sb + buf * 16384 + SW128(row * 128 + c16 * 16);
            CP_ASYNC16(da, (const void*)(Abase + (size_t)row * K2_ + kc + c16 * 8));
        }
#pragma unroll
        for (int i = 0; i < 4; i++) {
            int flat = i * 256 + tid, row = flat >> 3, c16 = flat & 7;
            uint32_t db = sb + 32768 + buf * 16384 + SW128(row * 128 + c16 * 16);
            CP_ASYNC16(db, (const void*)(Bbase + (size_t)row * K2_ + kc + c16 * 8));
        }
        CP_COMMIT();
    };

    issue(0, 0);

    for (int c = 0; c < NCH_; c++) {
        const int buf = c & 1;
        if (c + 1 < NCH_) { issue(c + 1, buf ^ 1); CP_WAIT1(); }
        else              { CP_WAIT0(); }
        __syncthreads();

        const uint32_t Aoff = sb + buf * 16384;
        const uint32_t Boff = sb + 32768 + buf * 16384;
        const int arow = warp_m + (lane & 15);
        const int brow = warp_n + (lane & 7) + ((lane & 16) ? 8 : 0);
        const int akb  = (lane & 16) ? 16 : 0;
        const int bkb  = (lane & 8) ? 16 : 0;

#pragma unroll
        for (int ks = 0; ks < 4; ks++) {
            uint32_t a[2][4];
#pragma unroll
            for (int mt = 0; mt < 2; mt++)
                LDSM_X4(a[mt][0], a[mt][1], a[mt][2], a[mt][3],
                        Aoff + SW128((arow + mt * 16) * 128 + ks * 32 + akb));
            uint32_t b[8][2];
#pragma unroll
            for (int bt = 0; bt < 4; bt++) {
                uint32_t r0, r1, r2, r3;
                LDSM_X4(r0, r1, r2, r3,
                        Boff + SW128((brow + bt * 16) * 128 + ks * 32 + bkb));
                b[bt * 2][0] = r0; b[bt * 2][1] = r1;
                b[bt * 2 + 1][0] = r2; b[bt * 2 + 1][1] = r3;
            }
#pragma unroll
            for (int mt = 0; mt < 2; mt++)
#pragma unroll
                for (int nt = 0; nt < 8; nt++)
                    MMA16816(acc[mt][nt], a[mt], b[nt]);
        }
        __syncthreads();
    }

    float* st = (float*)smp;
#pragma unroll
    for (int mt = 0; mt < 2; mt++)
#pragma unroll
        for (int nt = 0; nt < 8; nt++) {
            const int m = warp_m + mt * 16 + (lane >> 2);
            const int n = warp_n + nt * 8 + 2 * (lane & 3);
            st[n * 132 + m]           = acc[mt][nt][0];
            st[(n + 1) * 132 + m]     = acc[mt][nt][1];
            st[n * 132 + m + 8]       = acc[mt][nt][2];
            st[(n + 1) * 132 + m + 8] = acc[mt][nt][3];
        }
    __syncthreads();

#pragma unroll 4
    for (int it = 0; it < 64; it++) {
        int flat = it * 256 + tid;
        int m = flat & 127, n = flat >> 7;
        float v = st[n * 132 + m] + __ldg(bi + n0 + n);
        g_gx[(size_t)(bm * 2 + (m >> 6)) * (G_ * B_) + (size_t)(n0 + n) * B_ + (m & 63)] = v;
    }
}

// ---------------- Phase 2: recurrence v5 (HMMA, 128 CTAs, M=32 N=32) ----------------
// CTA: j0 = (bx>>1)*8 states, mb = (bx&1)*32 batches.
// smem: A [32][1024]f16 (65536) | W [32][1024]f16 (65536) | gates [32][34]f32 (4352)
//       | gx [32][32]f32 (4096) | hst hi/lo 512B+512B + hstf 1024B
#define A_OFF   0
#define W_OFF   65536
#define G_OFF   131072
#define GX_OFF  135424
#define HST_OFF 139520
#define SMEM_LSTM 141568

__global__ __launch_bounds__(256, 1) void lstm_kernel(
    const float* __restrict__ bh, float* __restrict__ out)
{
    extern __shared__ char smp[];
    const uint32_t sb = smem_u32(smp);
    float*  gates_s = (float*)(smp + G_OFF);
    float*  gx_s    = (float*)(smp + GX_OFF);
    __half* hst     = (__half*)(smp + HST_OFF);           // hi[256], lo[256]
    float*  hstf    = (float*)(smp + HST_OFF + 1024);     // [32][8]

    const int tid = threadIdx.x, wid = tid >> 5, lane = tid & 31;
    const int j0 = (blockIdx.x >> 1) * 8;
    const int mb = (blockIdx.x & 1) * 32;

    // preload W slice, h(0), gx(0)
    {
#pragma unroll
        for (int i = 0; i < 16; i++) {
            int q = i * 256 + tid;             // 4096
            int lrow = q >> 7, c16 = q & 127;
            int g = lrow >> 3, jl = lrow & 7;
            CP_ASYNC16(sb + W_OFF + lrow * 2048 + (((uint32_t)(c16 ^ (lrow & 7))) << 4),
                       (const void*)(g_w2 + (size_t)(g * 512 + j0 + jl) * 1024 + c16 * 8));
        }
#pragma unroll
        for (int i = 0; i < 16; i++) {
            int q = i * 256 + tid;             // 4096
            int r = q >> 7, c16 = q & 127;
            CP_ASYNC16(sb + A_OFF + r * 2048 + (((uint32_t)(c16 ^ (r & 7))) << 4),
                       (const void*)(g_h2[0] + (size_t)(mb + r) * 1024 + c16 * 8));
        }
        {
            int n = tid >> 3, c = tid & 7;
            int g = n >> 3, jl = n & 7;
            CP_ASYNC16(sb + GX_OFF + (uint32_t)(n * 32 + c * 4) * 4,
                       (const void*)(g_gx + (size_t)(g * 512 + j0 + jl) * 64 + mb + c * 4));
        }
        CP_COMMIT();
        CP_WAIT0();
    }
    __syncthreads();

    // pointwise mapping: thread = (pjl 0..7, pb 0..31)
    const int pjl = tid >> 5;
    const int pb  = tid & 31;
    float bias[4];
#pragma unroll
    for (int g = 0; g < 4; g++) bias[g] = bh[g * 512 + j0 + pjl];
    float cs = 0.f;

    // mma mapping: warp = (mt 0..1, ng 0..3)
    const int mt = wid & 1, ng = wid >> 1;
    const int arow = mt * 16 + (lane & 15);
    const int abit = (lane >> 4) & 1;
    const uint32_t abase = sb + A_OFF + arow * 2048;
    const uint32_t aph = (uint32_t)(arow & 7);
    const int brow = ng * 8 + (lane & 7);
    const int bq   = lane >> 3;           // 0..3
    const uint32_t bbase = sb + W_OFF + brow * 2048;
    const uint32_t bph = (uint32_t)(brow & 7);

    for (int t = 0; t < S_; t++) {
        float acc[4] = {0.f, 0.f, 0.f, 0.f};
        // pass 1: A = [h_hi|h_lo] c16 0..127, B = w_hi (cycled twice)
#pragma unroll 8
        for (int ksd = 0; ksd < 32; ksd++) {
            uint32_t ca0 = (uint32_t)(ksd * 4 + abit);
            uint32_t ca1 = (uint32_t)(ksd * 4 + 2 + abit);
            uint32_t cb  = (uint32_t)(((ksd & 15) * 4) + bq);
            uint32_t a00, a01, a02, a03, a10, a11, a12, a13, b0, b1, b2, b3;
            LDSM_X4(a00, a01, a02, a03, abase + ((ca0 ^ aph) << 4));
            LDSM_X4(a10, a11, a12, a13, abase + ((ca1 ^ aph) << 4));
            LDSM_X4(b0, b1, b2, b3, bbase + ((cb ^ bph) << 4));
            uint32_t av0[4] = {a00, a01, a02, a03};
            uint32_t av1[4] = {a10, a11, a12, a13};
            uint32_t bv0[2] = {b0, b1}, bv1[2] = {b2, b3};
            MMA16816(acc, av0, bv0);
            MMA16816(acc, av1, bv1);
        }
        // pass 2: A = h_hi c16 0..63, B = w_lo c16 64..127
#pragma unroll 8
        for (int ksd = 0; ksd < 16; ksd++) {
            uint32_t ca0 = (uint32_t)(ksd * 4 + abit);
            uint32_t ca1 = (uint32_t)(ksd * 4 + 2 + abit);
            uint32_t cb  = (uint32_t)(64 + ksd * 4 + bq);
            uint32_t a00, a01, a02, a03, a10, a11, a12, a13, b0, b1, b2, b3;
            LDSM_X4(a00, a01, a02, a03, abase + ((ca0 ^ aph) << 4));
            LDSM_X4(a10, a11, a12, a13, abase + ((ca1 ^ aph) << 4));
            LDSM_X4(b0, b1, b2, b3, bbase + ((cb ^ bph) << 4));
            uint32_t av0[4] = {a00, a01, a02, a03};
            uint32_t av1[4] = {a10, a11, a12, a13};
            uint32_t bv0[2] = {b0, b1}, bv1[2] = {b2, b3};
            MMA16816(acc, av0, bv0);
            MMA16816(acc, av1, bv1);
        }

        // frags -> gates_s[n][m]
        {
            const int fm = mt * 16 + (lane >> 2);
            const int fn = ng * 8 + 2 * (lane & 3);
            gates_s[fn * 34 + fm]           = acc[0];
            gates_s[(fn + 1) * 34 + fm]     = acc[1];
            gates_s[fn * 34 + fm + 8]       = acc[2];
            gates_s[(fn + 1) * 34 + fm + 8] = acc[3];
        }
        __syncthreads();

        // fused pointwise: n = g*8 + pjl
        float pre[4];
#pragma unroll
        for (int g = 0; g < 4; g++) {
            int n = g * 8 + pjl;
            pre[g] = gates_s[n * 34 + pb] + gx_s[n * 32 + pb] + bias[g];
        }
        float iv = 1.f / (1.f + __expf(-pre[0]));
        float fv = 1.f / (1.f + __expf(-pre[1]));
        float gv = tanhf(pre[2]);
        float ov = 1.f / (1.f + __expf(-pre[3]));
        cs = fv * cs + iv * gv;
        float hv = ov * tanhf(cs);

        if (t == S_ - 1) {
            const size_t ob = (size_t)B_ * S_ * H4_;
            out[((size_t)(mb + pb) * S_ + t) * H4_ + j0 + pjl] = hv;
            out[ob + (size_t)(mb + pb) * H4_ + j0 + pjl] = hv;
            out[ob + (size_t)B_ * H4_ + (size_t)(mb + pb) * H4_ + j0 + pjl] = cs;
            continue;
        }

        // stage h (hi/lo fp16 + fp32 for out)
        {
            __half hh = __float2half_rn(hv);
            __half hl = __float2half_rn(hv - __half2float(hh));
            hst[pb * 8 + pjl]       = hh;
            hst[256 + pb * 8 + pjl] = hl;
            hstf[pb * 8 + pjl]      = hv;
        }
        __syncthreads();

        // publish h(t+1)
        const int buf = (t + 1) & 1;
        if (tid < 32) {
            *(float4*)(g_h2[buf] + (size_t)(mb + tid) * 1024 + j0) = *(float4*)(hst + tid * 8);
        } else if (tid < 64) {
            int b = tid - 32;
            *(float4*)(g_h2[buf] + (size_t)(mb + b) * 1024 + 512 + j0) = *(float4*)(hst + 256 + b * 8);
        }
        __syncthreads();

        if (tid == 0)
            asm volatile("red.release.gpu.global.add.u32 [%0], %1;"
                         :: "l"(&g_cnt), "r"(1u) : "memory");

        // overlap: coalesced out stores for step t (32B per row)
        if (tid < 32) {
            float* dst = out + ((size_t)(mb + tid) * S_ + t) * H4_ + j0;
            *(float4*)dst       = *(float4*)(hstf + tid * 8);
            *(float4*)(dst + 4) = *(float4*)(hstf + tid * 8 + 4);
        }

        // barrier wait
        const unsigned tgt = (unsigned)(t + 1) * NCTA2;
        unsigned v;
        do {
            asm volatile("ld.acquire.gpu.global.u32 %0, [%1];"
                         : "=r"(v) : "l"(&g_cnt) : "memory");
        } while (v < tgt);

        // fetch h(t+1) and gx(t+1)
#pragma unroll
        for (int i = 0; i < 16; i++) {
            int q = i * 256 + tid;
            int r = q >> 7, c16 = q & 127;
            CP_ASYNC16(sb + A_OFF + r * 2048 + (((uint32_t)(c16 ^ (r & 7))) << 4),
                       (const void*)(g_h2[buf] + (size_t)(mb + r) * 1024 + c16 * 8));
        }
        {
            int n = tid >> 3, c = tid & 7;
            int g = n >> 3, jl = n & 7;
            CP_ASYNC16(sb + GX_OFF + (uint32_t)(n * 32 + c * 4) * 4,
                       (const void*)(g_gx + (size_t)(t + 1) * (G_ * B_)
                                     + (size_t)(g * 512 + j0 + jl) * 64 + mb + c * 4));
        }
        CP_COMMIT();
        CP_WAIT0();
        __syncthreads();
    }
}

extern "C" void kernel_launch(void* const* d_in, const int* in_sizes, int n_in,
                              void* d_out, int out_size) {
    const float* X  = (const float*)d_in[0];
    const float* Wi = (const float*)d_in[1];
    const float* Wh = (const float*)d_in[2];
    const float* bi = (const float*)d_in[3];
    const float* bh = (const float*)d_in[4];
    float* out = (float*)d_out;

    cudaFuncSetAttribute(gemm_hmma_kernel, cudaFuncAttributeMaxDynamicSharedMemorySize, SMEM_GEMM);
    cudaFuncSetAttribute(lstm_kernel, cudaFuncAttributeMaxDynamicSharedMemorySize, SMEM_LSTM);

    conv_a_kernel<<<32768, 256>>>(X);
    conv_b_kernel<<<1024, 256>>>(Wi);
    conv_w_kernel<<<1024, 256>>>(Wh);
    gemm_hmma_kernel<<<dim3(16, 512), 256, SMEM_GEMM>>>(bi);
    lstm_kernel<<<NCTA2, 256, SMEM_LSTM>>>(bh, out);
}

// round 16
// speedup vs baseline: 2.3598x; 1.1963x over previous
#include <cuda_runtime.h>
#include <cuda_fp16.h>
#include <cstdint>

#define B_   64
#define S_   1024
#define IN_  512
#define H4_  512
#define G_   2048
#define NCTA2 128
#define K2_  1536
#define NCH_ 24

__device__ float    g_gx[(size_t)S_ * G_ * B_];   // [s][n][b]
__device__ __half   g_a2[(size_t)S_ * B_ * K2_];  // [m=s*64+b][k']
__device__ __half   g_b2[(size_t)G_ * K2_];       // [n][k']
__device__ __half   g_w2[(size_t)G_ * 1024];      // Wh hi|lo  [row][k']
__device__ __half   g_h2[2][64 * 1024];           // h hi|lo   [b][k']
__device__ unsigned g_cnt2[2][32];                // per-mb-group barrier (padded)

__device__ __forceinline__ uint32_t smem_u32(const void* p) {
    uint32_t a;
    asm("{ .reg .u64 t; cvta.to.shared.u64 t, %1; cvt.u32.u64 %0, t; }" : "=r"(a) : "l"(p));
    return a;
}
#define SW128(x) ((x) ^ (((x) >> 3) & 0x70))

#define LDSM_X4(r0, r1, r2, r3, addr) \
    asm volatile("ldmatrix.sync.aligned.m8n8.x4.shared.b16 {%0,%1,%2,%3}, [%4];" \
        : "=r"(r0), "=r"(r1), "=r"(r2), "=r"(r3) : "r"(addr))

#define MMA16816(d, a, b) \
    asm volatile("mma.sync.aligned.m16n8k16.row.col.f32.f16.f16.f32 " \
        "{%0,%1,%2,%3}, {%4,%5,%6,%7}, {%8,%9}, {%0,%1,%2,%3};" \
        : "+f"(d[0]), "+f"(d[1]), "+f"(d[2]), "+f"(d[3]) \
        : "r"(a[0]), "r"(a[1]), "r"(a[2]), "r"(a[3]), "r"(b[0]), "r"(b[1]))

#define CP_ASYNC16(dst, src) \
    asm volatile("cp.async.cg.shared.global [%0], [%1], 16;" :: "r"(dst), "l"(src) : "memory")
#define CP_COMMIT() asm volatile("cp.async.commit_group;" ::: "memory")
#define CP_WAIT1()  asm volatile("cp.async.wait_group 1;" ::: "memory")
#define CP_WAIT0()  asm volatile("cp.async.wait_group 0;" ::: "memory")

// ---------------- conversions ----------------
__global__ __launch_bounds__(256) void conv_a_kernel(const float* __restrict__ X) {
    size_t gtid = (size_t)blockIdx.x * 256 + threadIdx.x;
    if (gtid < 2) { g_cnt2[gtid][0] = 0u; }
    if (gtid < 8192) ((float4*)g_h2[0])[gtid] = make_float4(0.f, 0.f, 0.f, 0.f);
    int k4 = (int)(gtid & 127);
    size_t row = gtid >> 7;              // b*1024 + s
    int b = (int)(row >> 10), s = (int)(row & 1023);
    float4 x = *(const float4*)(X + row * 512 + k4 * 4);
    float xv[4] = { x.x, x.y, x.z, x.w };
    __half h[4], l[4];
#pragma unroll
    for (int i = 0; i < 4; i++) {
        h[i] = __float2half_rn(xv[i]);
        l[i] = __float2half_rn(xv[i] - __half2float(h[i]));
    }
    size_t m = (size_t)s * 64 + b;
    __half* base = g_a2 + m * K2_ + k4 * 4;
    __half2 h01 = __halves2half2(h[0], h[1]), h23 = __halves2half2(h[2], h[3]);
    __half2 l01 = __halves2half2(l[0], l[1]), l23 = __halves2half2(l[2], l[3]);
    *(__half2*)(base + 0) = h01;        *(__half2*)(base + 2) = h23;
    *(__half2*)(base + 512) = h01;      *(__half2*)(base + 514) = h23;
    *(__half2*)(base + 1024) = l01;     *(__half2*)(base + 1026) = l23;
}

__global__ __launch_bounds__(256) void conv_b_kernel(const float* __restrict__ Wi) {
    size_t gtid = (size_t)blockIdx.x * 256 + threadIdx.x;
    int k4 = (int)(gtid & 127);
    size_t n = gtid >> 7;
    float4 x = *(const float4*)(Wi + n * 512 + k4 * 4);
    float xv[4] = { x.x, x.y, x.z, x.w };
    __half h[4], l[4];
#pragma unroll
    for (int i = 0; i < 4; i++) {
        h[i] = __float2half_rn(xv[i]);
        l[i] = __float2half_rn(xv[i] - __half2float(h[i]));
    }
    __half* base = g_b2 + n * K2_ + k4 * 4;
    *(__half2*)(base + 0)    = __halves2half2(h[0], h[1]);
    *(__half2*)(base + 2)    = __halves2half2(h[2], h[3]);
    *(__half2*)(base + 512)  = __halves2half2(l[0], l[1]);
    *(__half2*)(base + 514)  = __halves2half2(l[2], l[3]);
    *(__half2*)(base + 1024) = __halves2half2(h[0], h[1]);
    *(__half2*)(base + 1026) = __halves2half2(h[2], h[3]);
}

__global__ __launch_bounds__(256) void conv_w_kernel(const float* __restrict__ Wh) {
    size_t gtid = (size_t)blockIdx.x * 256 + threadIdx.x;   // 262144
    int k4 = (int)(gtid & 127);
    size_t n = gtid >> 7;                // gate row 0..2047
    float4 x = *(const float4*)(Wh + n * 512 + k4 * 4);
    float xv[4] = { x.x, x.y, x.z, x.w };
    __half h[4], l[4];
#pragma unroll
    for (int i = 0; i < 4; i++) {
        h[i] = __float2half_rn(xv[i]);
        l[i] = __float2half_rn(xv[i] - __half2float(h[i]));
    }
    __half* base = g_w2 + n * 1024 + k4 * 4;
    *(__half2*)(base + 0)   = __halves2half2(h[0], h[1]);
    *(__half2*)(base + 2)   = __halves2half2(h[2], h[3]);
    *(__half2*)(base + 512) = __halves2half2(l[0], l[1]);
    *(__half2*)(base + 514) = __halves2half2(l[2], l[3]);
}

// ---------------- Phase 1: HMMA GEMM, tile M=128 N=128 K=1536 ----------------
#define SMEM_GEMM 67584

__global__ __launch_bounds__(256, 2) void gemm_hmma_kernel(const float* __restrict__ bi) {
    extern __shared__ char smp[];
    const uint32_t sb = smem_u32(smp);
    const int tid = threadIdx.x, wid = tid >> 5, lane = tid & 31;
    const int n0 = blockIdx.x * 128;
    const int bm = blockIdx.y;

    const __half* Abase = g_a2 + (size_t)bm * 128 * K2_;
    const __half* Bbase = g_b2 + (size_t)n0 * K2_;

    const int warp_m = (wid & 1) * 64 + (wid >> 2) * 32;
    const int warp_n = ((wid >> 1) & 1) * 64;

    float acc[2][8][4];
#pragma unroll
    for (int mt = 0; mt < 2; mt++)
#pragma unroll
        for (int nt = 0; nt < 8; nt++)
#pragma unroll
            for (int q = 0; q < 4; q++) acc[mt][nt][q] = 0.f;

    auto issue = [&](int c, int buf) {
        const int kc = c * 64;
#pragma unroll
        for (int i = 0; i < 4; i++) {
            int flat = i * 256 + tid, row = flat >> 3, c16 = flat & 7;
            uint32_t da = sb + buf * 16384 + SW128(row * 128 + c16 * 16);
            CP_ASYNC16(da, (const void*)(Abase + (size_t)row * K2_ + kc + c16 * 8));
        }
#pragma unroll
        for (int i = 0; i < 4; i++) {
            int flat = i * 256 + tid, row = flat >> 3, c16 = flat & 7;
            uint32_t db = sb + 32768 + buf * 16384 + SW128(row * 128 + c16 * 16);
            CP_ASYNC16(db, (const void*)(Bbase + (size_t)row * K2_ + kc + c16 * 8));
        }
        CP_COMMIT();
    };

    issue(0, 0);

    for (int c = 0; c < NCH_; c++) {
        const int buf = c & 1;
        if (c + 1 < NCH_) { issue(c + 1, buf ^ 1); CP_WAIT1(); }
        else              { CP_WAIT0(); }
        __syncthreads();

        const uint32_t Aoff = sb + buf * 16384;
        const uint32_t Boff = sb + 32768 + buf * 16384;
        const int arow = warp_m + (lane & 15);
        const int brow = warp_n + (lane & 7) + ((lane & 16) ? 8 : 0);
        const int akb  = (lane & 16) ? 16 : 0;
        const int bkb  = (lane & 8) ? 16 : 0;

#pragma unroll
        for (int ks = 0; ks < 4; ks++) {
            uint32_t a[2][4];
#pragma unroll
            for (int mt = 0; mt < 2; mt++)
                LDSM_X4(a[mt][0], a[mt][1], a[mt][2], a[mt][3],
                        Aoff + SW128((arow + mt * 16) * 128 + ks * 32 + akb));
            uint32_t b[8][2];
#pragma unroll
            for (int bt = 0; bt < 4; bt++) {
                uint32_t r0, r1, r2, r3;
                LDSM_X4(r0, r1, r2, r3,
                        Boff + SW128((brow + bt * 16) * 128 + ks * 32 + bkb));
                b[bt * 2][0] = r0; b[bt * 2][1] = r1;
                b[bt * 2 + 1][0] = r2; b[bt * 2 + 1][1] = r3;
            }
#pragma unroll
            for (int mt = 0; mt < 2; mt++)
#pragma unroll
                for (int nt = 0; nt < 8; nt++)
                    MMA16816(acc[mt][nt], a[mt], b[nt]);
        }
        __syncthreads();
    }

    float* st = (float*)smp;
#pragma unroll
    for (int mt = 0; mt < 2; mt++)
#pragma unroll
        for (int nt = 0; nt < 8; nt++) {
            const int m = warp_m + mt * 16 + (lane >> 2);
            const int n = warp_n + nt * 8 + 2 * (lane & 3);
            st[n * 132 + m]           = acc[mt][nt][0];
            st[(n + 1) * 132 + m]     = acc[mt][nt][1];
            st[n * 132 + m + 8]       = acc[mt][nt][2];
            st[(n + 1) * 132 + m + 8] = acc[mt][nt][3];
        }
    __syncthreads();

#pragma unroll 4
    for (int it = 0; it < 64; it++) {
        int flat = it * 256 + tid;
        int m = flat & 127, n = flat >> 7;
        float v = st[n * 132 + m] + __ldg(bi + n0 + n);
        g_gx[(size_t)(bm * 2 + (m >> 6)) * (G_ * B_) + (size_t)(n0 + n) * B_ + (m & 63)] = v;
    }
}

// ---------------- Phase 2: recurrence v6 ----------------
// 128 CTAs; CTA: j0=(bx>>1)*8 states, mb=(bx&1)*32 batches. Two independent
// 64-CTA barrier groups (one per mb half).
#define A_OFF   0
#define W_OFF   65536
#define G_OFF   131072
#define GX_OFF  135424
#define HST_OFF 139520
#define SMEM_LSTM 141568

__global__ __launch_bounds__(256, 1) void lstm_kernel(
    const float* __restrict__ bh, float* __restrict__ out)
{
    extern __shared__ char smp[];
    const uint32_t sb = smem_u32(smp);
    float*  gates_s = (float*)(smp + G_OFF);
    float*  gx_s    = (float*)(smp + GX_OFF);
    __half* hst     = (__half*)(smp + HST_OFF);           // hi[256], lo[256]
    float*  hstf    = (float*)(smp + HST_OFF + 1024);     // [32][8]

    const int tid = threadIdx.x, wid = tid >> 5, lane = tid & 31;
    const int j0 = (blockIdx.x >> 1) * 8;
    const int mb = (blockIdx.x & 1) * 32;
    unsigned* cnt = &g_cnt2[blockIdx.x & 1][0];

    // preload W slice, h(0), gx(0)
    {
#pragma unroll
        for (int i = 0; i < 16; i++) {
            int q = i * 256 + tid;
            int lrow = q >> 7, c16 = q & 127;
            int g = lrow >> 3, jl = lrow & 7;
            CP_ASYNC16(sb + W_OFF + lrow * 2048 + (((uint32_t)(c16 ^ (lrow & 7))) << 4),
                       (const void*)(g_w2 + (size_t)(g * 512 + j0 + jl) * 1024 + c16 * 8));
        }
#pragma unroll
        for (int i = 0; i < 16; i++) {
            int q = i * 256 + tid;
            int r = q >> 7, c16 = q & 127;
            CP_ASYNC16(sb + A_OFF + r * 2048 + (((uint32_t)(c16 ^ (r & 7))) << 4),
                       (const void*)(g_h2[0] + (size_t)(mb + r) * 1024 + c16 * 8));
        }
        {
            int n = tid >> 3, c = tid & 7;
            int g = n >> 3, jl = n & 7;
            CP_ASYNC16(sb + GX_OFF + (uint32_t)(n * 32 + c * 4) * 4,
                       (const void*)(g_gx + (size_t)(g * 512 + j0 + jl) * 64 + mb + c * 4));
        }
        CP_COMMIT();
        CP_WAIT0();
    }
    __syncthreads();

    const int pjl = tid >> 5;
    const int pb  = tid & 31;
    float bias[4];
#pragma unroll
    for (int g = 0; g < 4; g++) bias[g] = bh[g * 512 + j0 + pjl];
    float cs = 0.f;

    const int mt = wid & 1, ng = wid >> 1;
    const int arow = mt * 16 + (lane & 15);
    const int abit = (lane >> 4) & 1;
    const uint32_t abase = sb + A_OFF + arow * 2048;
    const uint32_t aph = (uint32_t)(arow & 7);
    const int brow = ng * 8 + (lane & 7);
    const int bq   = lane >> 3;
    const uint32_t bbase = sb + W_OFF + brow * 2048;
    const uint32_t bph = (uint32_t)(brow & 7);

    for (int t = 0; t < S_; t++) {
        float acc[4][4];
#pragma unroll
        for (int i = 0; i < 4; i++)
#pragma unroll
            for (int q = 0; q < 4; q++) acc[i][q] = 0.f;

        // pass 1: B=w_hi loaded once, used for both h_hi (c16 0..63) and h_lo (64..127)
#pragma unroll 4
        for (int ksd2 = 0; ksd2 < 16; ksd2++) {
            uint32_t cb  = (uint32_t)(ksd2 * 4 + bq);
            uint32_t b0, b1, b2, b3;
            LDSM_X4(b0, b1, b2, b3, bbase + ((cb ^ bph) << 4));
            uint32_t bv0[2] = {b0, b1}, bv1[2] = {b2, b3};

            uint32_t ca0 = (uint32_t)(ksd2 * 4 + abit);
            uint32_t ca1 = (uint32_t)(ksd2 * 4 + 2 + abit);
            uint32_t h00, h01, h02, h03, h10, h11, h12, h13;
            LDSM_X4(h00, h01, h02, h03, abase + ((ca0 ^ aph) << 4));
            LDSM_X4(h10, h11, h12, h13, abase + ((ca1 ^ aph) << 4));
            uint32_t hv0[4] = {h00, h01, h02, h03};
            uint32_t hv1[4] = {h10, h11, h12, h13};
            MMA16816(acc[0], hv0, bv0);
            MMA16816(acc[1], hv1, bv1);

            uint32_t la0 = ca0 + 64, la1 = ca1 + 64;
            uint32_t l00, l01, l02, l03, l10, l11, l12, l13;
            LDSM_X4(l00, l01, l02, l03, abase + ((la0 ^ aph) << 4));
            LDSM_X4(l10, l11, l12, l13, abase + ((la1 ^ aph) << 4));
            uint32_t lv0[4] = {l00, l01, l02, l03};
            uint32_t lv1[4] = {l10, l11, l12, l13};
            MMA16816(acc[2], lv0, bv0);
            MMA16816(acc[3], lv1, bv1);
        }
        // pass 2: A=h_hi (c16 0..63), B=w_lo (c16 64..127)
#pragma unroll 4
        for (int ksd2 = 0; ksd2 < 16; ksd2++) {
            uint32_t cb  = (uint32_t)(64 + ksd2 * 4 + bq);
            uint32_t b0, b1, b2, b3;
            LDSM_X4(b0, b1, b2, b3, bbase + ((cb ^ bph) << 4));
            uint32_t bv0[2] = {b0, b1}, bv1[2] = {b2, b3};

            uint32_t ca0 = (uint32_t)(ksd2 * 4 + abit);
            uint32_t ca1 = (uint32_t)(ksd2 * 4 + 2 + abit);
            uint32_t h00, h01, h02, h03, h10, h11, h12, h13;
            LDSM_X4(h00, h01, h02, h03, abase + ((ca0 ^ aph) << 4));
            LDSM_X4(h10, h11, h12, h13, abase + ((ca1 ^ aph) << 4));
            uint32_t hv0[4] = {h00, h01, h02, h03};
            uint32_t hv1[4] = {h10, h11, h12, h13};
            MMA16816(acc[0], hv0, bv0);
            MMA16816(acc[1], hv1, bv1);
        }

        // frags -> gates_s[n][m]
        {
            const int fm = mt * 16 + (lane >> 2);
            const int fn = ng * 8 + 2 * (lane & 3);
            float r0 = acc[0][0] + acc[1][0] + acc[2][0] + acc[3][0];
            float r1 = acc[0][1] + acc[1][1] + acc[2][1] + acc[3][1];
            float r2 = acc[0][2] + acc[1][2] + acc[2][2] + acc[3][2];
            float r3 = acc[0][3] + acc[1][3] + acc[2][3] + acc[3][3];
            gates_s[fn * 34 + fm]           = r0;
            gates_s[(fn + 1) * 34 + fm]     = r1;
            gates_s[fn * 34 + fm + 8]       = r2;
            gates_s[(fn + 1) * 34 + fm + 8] = r3;
        }
        __syncthreads();

        // fused pointwise
        float pre[4];
#pragma unroll
        for (int g = 0; g < 4; g++) {
            int n = g * 8 + pjl;
            pre[g] = gates_s[n * 34 + pb] + gx_s[n * 32 + pb] + bias[g];
        }
        float iv = 1.f / (1.f + __expf(-pre[0]));
        float fv = 1.f / (1.f + __expf(-pre[1]));
        float gv = tanhf(pre[2]);
        float ov = 1.f / (1.f + __expf(-pre[3]));
        cs = fv * cs + iv * gv;
        float hv = ov * tanhf(cs);

        if (t == S_ - 1) {
            const size_t ob = (size_t)B_ * S_ * H4_;
            out[((size_t)(mb + pb) * S_ + t) * H4_ + j0 + pjl] = hv;
            out[ob + (size_t)(mb + pb) * H4_ + j0 + pjl] = hv;
            out[ob + (size_t)B_ * H4_ + (size_t)(mb + pb) * H4_ + j0 + pjl] = cs;
            continue;
        }

        // stage h
        {
            __half hh = __float2half_rn(hv);
            __half hl = __float2half_rn(hv - __half2float(hh));
            hst[pb * 8 + pjl]       = hh;
            hst[256 + pb * 8 + pjl] = hl;
            hstf[pb * 8 + pjl]      = hv;
        }
        __syncthreads();

        // publish h(t+1)
        const int buf = (t + 1) & 1;
        if (tid < 32) {
            *(float4*)(g_h2[buf] + (size_t)(mb + tid) * 1024 + j0) = *(float4*)(hst + tid * 8);
        } else if (tid < 64) {
            int b = tid - 32;
            *(float4*)(g_h2[buf] + (size_t)(mb + b) * 1024 + 512 + j0) = *(float4*)(hst + 256 + b * 8);
        }
        __syncthreads();

        // gx(t+1) prefetch (independent of barrier)
        {
            int n = tid >> 3, c = tid & 7;
            int g = n >> 3, jl = n & 7;
            CP_ASYNC16(sb + GX_OFF + (uint32_t)(n * 32 + c * 4) * 4,
                       (const void*)(g_gx + (size_t)(t + 1) * (G_ * B_)
                                     + (size_t)(g * 512 + j0 + jl) * 64 + mb + c * 4));
        }
        CP_COMMIT();

        // arrive + single-thread poll; out stores overlap in warp 1
        if (tid == 0)
            asm volatile("red.release.gpu.global.add.u32 [%0], %1;"
                         :: "l"(cnt), "r"(1u) : "memory");
        if (tid >= 32 && tid < 64) {
            int b = tid - 32;
            float* dst = out + ((size_t)(mb + b) * S_ + t) * H4_ + j0;
            *(float4*)dst       = *(float4*)(hstf + b * 8);
            *(float4*)(dst + 4) = *(float4*)(hstf + b * 8 + 4);
        }
        if (tid == 0) {
            const unsigned tgt = (unsigned)(t + 1) * 64u;
            unsigned v;
            do {
                asm volatile("ld.acquire.gpu.global.u32 %0, [%1];"
                             : "=r"(v) : "l"(cnt) : "memory");
            } while (v < tgt);
        }
        __syncthreads();

        // fetch h(t+1)
#pragma unroll
        for (int i = 0; i < 16; i++) {
            int q = i * 256 + tid;
            int r = q >> 7, c16 = q & 127;
            CP_ASYNC16(sb + A_OFF + r * 2048 + (((uint32_t)(c16 ^ (r & 7))) << 4),
                       (const void*)(g_h2[buf] + (size_t)(mb + r) * 1024 + c16 * 8));
        }
        CP_COMMIT();
        CP_WAIT0();
        __syncthreads();
    }
}

extern "C" void kernel_launch(void* const* d_in, const int* in_sizes, int n_in,
                              void* d_out, int out_size) {
    const float* X  = (const float*)d_in[0];
    const float* Wi = (const float*)d_in[1];
    const float* Wh = (const float*)d_in[2];
    const float* bi = (const float*)d_in[3];
    const float* bh = (const float*)d_in[4];
    float* out = (float*)d_out;

    cudaFuncSetAttribute(gemm_hmma_kernel, cudaFuncAttributeMaxDynamicSharedMemorySize, SMEM_GEMM);
    cudaFuncSetAttribute(lstm_kernel, cudaFuncAttributeMaxDynamicSharedMemorySize, SMEM_LSTM);

    conv_a_kernel<<<32768, 256>>>(X);
    conv_b_kernel<<<1024, 256>>>(Wi);
    conv_w_kernel<<<1024, 256>>>(Wh);
    gemm_hmma_kernel<<<dim3(16, 512), 256, SMEM_GEMM>>>(bi);
    lstm_kernel<<<NCTA2, 256, SMEM_LSTM>>>(bh, out);
}

// round 17
// speedup vs baseline: 2.5934x; 1.0990x over previous
#include <cuda_runtime.h>
#include <cuda_fp16.h>
#include <cstdint>

#define B_   64
#define S_   1024
#define IN_  512
#define H4_  512
#define G_   2048
#define NCTA2 128
#define K2_  1536
#define NCH_ 24

__device__ float    g_gx[(size_t)S_ * G_ * B_];   // [s][n][b]
__device__ __half   g_a2[(size_t)S_ * B_ * K2_];  // [m=s*64+b][k']
__device__ __half   g_b2[(size_t)G_ * K2_];       // [n][k']
__device__ __half   g_w2[(size_t)G_ * 1024];      // Wh hi|lo  [row][k']
__device__ uint4    g_fragh[2 * 2 * 2 * 32 * 32]; // [buf][mbh][mt][kc][lane] A-frag h_hi
__device__ uint4    g_fragl[2 * 2 * 2 * 32 * 32]; // same, h_lo
__device__ unsigned g_cnt2[2][32];                // per-mb-group barrier (padded)

__device__ __forceinline__ uint32_t smem_u32(const void* p) {
    uint32_t a;
    asm("{ .reg .u64 t; cvta.to.shared.u64 t, %1; cvt.u32.u64 %0, t; }" : "=r"(a) : "l"(p));
    return a;
}
#define SW128(x) ((x) ^ (((x) >> 3) & 0x70))

#define LDSM_X4(r0, r1, r2, r3, addr) \
    asm volatile("ldmatrix.sync.aligned.m8n8.x4.shared.b16 {%0,%1,%2,%3}, [%4];" \
        : "=r"(r0), "=r"(r1), "=r"(r2), "=r"(r3) : "r"(addr))

#define MMA16816(d, a, b) \
    asm volatile("mma.sync.aligned.m16n8k16.row.col.f32.f16.f16.f32 " \
        "{%0,%1,%2,%3}, {%4,%5,%6,%7}, {%8,%9}, {%0,%1,%2,%3};" \
        : "+f"(d[0]), "+f"(d[1]), "+f"(d[2]), "+f"(d[3]) \
        : "r"(a[0]), "r"(a[1]), "r"(a[2]), "r"(a[3]), "r"(b[0]), "r"(b[1]))

#define CP_ASYNC16(dst, src) \
    asm volatile("cp.async.cg.shared.global [%0], [%1], 16;" :: "r"(dst), "l"(src) : "memory")
#define CP_COMMIT() asm volatile("cp.async.commit_group;" ::: "memory")
#define CP_WAIT1()  asm volatile("cp.async.wait_group 1;" ::: "memory")
#define CP_WAIT0()  asm volatile("cp.async.wait_group 0;" ::: "memory")

#define LDG128CG(v, p) \
    asm volatile("ld.global.cg.v4.b32 {%0,%1,%2,%3}, [%4];" \
        : "=r"((v).x), "=r"((v).y), "=r"((v).z), "=r"((v).w) : "l"(p))

// ---------------- conversions ----------------
__global__ __launch_bounds__(256) void conv_a_kernel(const float* __restrict__ X) {
    size_t gtid = (size_t)blockIdx.x * 256 + threadIdx.x;
    if (gtid < 2) { g_cnt2[gtid][0] = 0u; }
    if (gtid < 8192) {
        g_fragh[gtid] = make_uint4(0u, 0u, 0u, 0u);
        g_fragl[gtid] = make_uint4(0u, 0u, 0u, 0u);
    }
    int k4 = (int)(gtid & 127);
    size_t row = gtid >> 7;              // b*1024 + s
    int b = (int)(row >> 10), s = (int)(row & 1023);
    float4 x = *(const float4*)(X + row * 512 + k4 * 4);
    float xv[4] = { x.x, x.y, x.z, x.w };
    __half h[4], l[4];
#pragma unroll
    for (int i = 0; i < 4; i++) {
        h[i] = __float2half_rn(xv[i]);
        l[i] = __float2half_rn(xv[i] - __half2float(h[i]));
    }
    size_t m = (size_t)s * 64 + b;
    __half* base = g_a2 + m * K2_ + k4 * 4;
    __half2 h01 = __halves2half2(h[0], h[1]), h23 = __halves2half2(h[2], h[3]);
    __half2 l01 = __halves2half2(l[0], l[1]), l23 = __halves2half2(l[2], l[3]);
    *(__half2*)(base + 0) = h01;        *(__half2*)(base + 2) = h23;
    *(__half2*)(base + 512) = h01;      *(__half2*)(base + 514) = h23;
    *(__half2*)(base + 1024) = l01;     *(__half2*)(base + 1026) = l23;
}

__global__ __launch_bounds__(256) void conv_b_kernel(const float* __restrict__ Wi) {
    size_t gtid = (size_t)blockIdx.x * 256 + threadIdx.x;
    int k4 = (int)(gtid & 127);
    size_t n = gtid >> 7;
    float4 x = *(const float4*)(Wi + n * 512 + k4 * 4);
    float xv[4] = { x.x, x.y, x.z, x.w };
    __half h[4], l[4];
#pragma unroll
    for (int i = 0; i < 4; i++) {
        h[i] = __float2half_rn(xv[i]);
        l[i] = __float2half_rn(xv[i] - __half2float(h[i]));
    }
    __half* base = g_b2 + n * K2_ + k4 * 4;
    *(__half2*)(base + 0)    = __halves2half2(h[0], h[1]);
    *(__half2*)(base + 2)    = __halves2half2(h[2], h[3]);
    *(__half2*)(base + 512)  = __halves2half2(l[0], l[1]);
    *(__half2*)(base + 514)  = __halves2half2(l[2], l[3]);
    *(__half2*)(base + 1024) = __halves2half2(h[0], h[1]);
    *(__half2*)(base + 1026) = __halves2half2(h[2], h[3]);
}

__global__ __launch_bounds__(256) void conv_w_kernel(const float* __restrict__ Wh) {
    size_t gtid = (size_t)blockIdx.x * 256 + threadIdx.x;   // 262144
    int k4 = (int)(gtid & 127);
    size_t n = gtid >> 7;                // gate row 0..2047
    float4 x = *(const float4*)(Wh + n * 512 + k4 * 4);
    float xv[4] = { x.x, x.y, x.z, x.w };
    __half h[4], l[4];
#pragma unroll
    for (int i = 0; i < 4; i++) {
        h[i] = __float2half_rn(xv[i]);
        l[i] = __float2half_rn(xv[i] - __half2float(h[i]));
    }
    __half* base = g_w2 + n * 1024 + k4 * 4;
    *(__half2*)(base + 0)   = __halves2half2(h[0], h[1]);
    *(__half2*)(base + 2)   = __halves2half2(h[2], h[3]);
    *(__half2*)(base + 512) = __halves2half2(l[0], l[1]);
    *(__half2*)(base + 514) = __halves2half2(l[2], l[3]);
}

// ---------------- Phase 1: HMMA GEMM, tile M=128 N=128 K=1536 ----------------
#define SMEM_GEMM 67584

__global__ __launch_bounds__(256, 2) void gemm_hmma_kernel(const float* __restrict__ bi) {
    extern __shared__ char smp[];
    const uint32_t sb = smem_u32(smp);
    const int tid = threadIdx.x, wid = tid >> 5, lane = tid & 31;
    const int n0 = blockIdx.x * 128;
    const int bm = blockIdx.y;

    const __half* Abase = g_a2 + (size_t)bm * 128 * K2_;
    const __half* Bbase = g_b2 + (size_t)n0 * K2_;

    const int warp_m = (wid & 1) * 64 + (wid >> 2) * 32;
    const int warp_n = ((wid >> 1) & 1) * 64;

    float acc[2][8][4];
#pragma unroll
    for (int mt = 0; mt < 2; mt++)
#pragma unroll
        for (int nt = 0; nt < 8; nt++)
#pragma unroll
            for (int q = 0; q < 4; q++) acc[mt][nt][q] = 0.f;

    auto issue = [&](int c, int buf) {
        const int kc = c * 64;
#pragma unroll
        for (int i = 0; i < 4; i++) {
            int flat = i * 256 + tid, row = flat >> 3, c16 = flat & 7;
            uint32_t da = sb + buf * 16384 + SW128(row * 128 + c16 * 16);
            CP_ASYNC16(da, (const void*)(Abase + (size_t)row * K2_ + kc + c16 * 8));
        }
#pragma unroll
        for (int i = 0; i < 4; i++) {
            int flat = i * 256 + tid, row = flat >> 3, c16 = flat & 7;
            uint32_t db = sb + 32768 + buf * 16384 + SW128(row * 128 + c16 * 16);
            CP_ASYNC16(db, (const void*)(Bbase + (size_t)row * K2_ + kc + c16 * 8));
        }
        CP_COMMIT();
    };

    issue(0, 0);

    for (int c = 0; c < NCH_; c++) {
        const int buf = c & 1;
        if (c + 1 < NCH_) { issue(c + 1, buf ^ 1); CP_WAIT1(); }
        else              { CP_WAIT0(); }
        __syncthreads();

        const uint32_t Aoff = sb + buf * 16384;
        const uint32_t Boff = sb + 32768 + buf * 16384;
        const int arow = warp_m + (lane & 15);
        const int brow = warp_n + (lane & 7) + ((lane & 16) ? 8 : 0);
        const int akb  = (lane & 16) ? 16 : 0;
        const int bkb  = (lane & 8) ? 16 : 0;

#pragma unroll
        for (int ks = 0; ks < 4; ks++) {
            uint32_t a[2][4];
#pragma unroll
            for (int mt = 0; mt < 2; mt++)
                LDSM_X4(a[mt][0], a[mt][1], a[mt][2], a[mt][3],
                        Aoff + SW128((arow + mt * 16) * 128 + ks * 32 + akb));
            uint32_t b[8][2];
#pragma unroll
            for (int bt = 0; bt < 4; bt++) {
                uint32_t r0, r1, r2, r3;
                LDSM_X4(r0, r1, r2, r3,
                        Boff + SW128((brow + bt * 16) * 128 + ks * 32 + bkb));
                b[bt * 2][0] = r0; b[bt * 2][1] = r1;
                b[bt * 2 + 1][0] = r2; b[bt * 2 + 1][1] = r3;
            }
#pragma unroll
            for (int mt = 0; mt < 2; mt++)
#pragma unroll
                for (int nt = 0; nt < 8; nt++)
                    MMA16816(acc[mt][nt], a[mt], b[nt]);
        }
        __syncthreads();
    }

    float* st = (float*)smp;
#pragma unroll
    for (int mt = 0; mt < 2; mt++)
#pragma unroll
        for (int nt = 0; nt < 8; nt++) {
            const int m = warp_m + mt * 16 + (lane >> 2);
            const int n = warp_n + nt * 8 + 2 * (lane & 3);
            st[n * 132 + m]           = acc[mt][nt][0];
            st[(n + 1) * 132 + m]     = acc[mt][nt][1];
            st[n * 132 + m + 8]       = acc[mt][nt][2];
            st[(n + 1) * 132 + m + 8] = acc[mt][nt][3];
        }
    __syncthreads();

#pragma unroll 4
    for (int it = 0; it < 64; it++) {
        int flat = it * 256 + tid;
        int m = flat & 127, n = flat >> 7;
        float v = st[n * 132 + m] + __ldg(bi + n0 + n);
        g_gx[(size_t)(bm * 2 + (m >> 6)) * (G_ * B_) + (size_t)(n0 + n) * B_ + (m & 63)] = v;
    }
}

// ---------------- Phase 2: recurrence v7 (fragment-layout h, direct LDG) ----------------
// smem: W [32][1024]f16 (65536) | gates [32][34]f32 (4352) | gx [32][32]f32 (4096)
//       | hst hi/lo 1024B | hstf 1024B
#define W_OFF   0
#define G_OFF   65536
#define GX_OFF  (G_OFF + 4352)
#define HST_OFF (GX_OFF + 4096)
#define SMEM_LSTM (HST_OFF + 2048)

__global__ __launch_bounds__(256, 1) void lstm_kernel(
    const float* __restrict__ bh, float* __restrict__ out)
{
    extern __shared__ char smp[];
    const uint32_t sb = smem_u32(smp);
    float*  gates_s = (float*)(smp + G_OFF);
    float*  gx_s    = (float*)(smp + GX_OFF);
    __half* hst     = (__half*)(smp + HST_OFF);           // hi[256], lo[256]
    float*  hstf    = (float*)(smp + HST_OFF + 1024);     // [32][8]

    const int tid = threadIdx.x, wid = tid >> 5, lane = tid & 31;
    const int j0  = (blockIdx.x >> 1) * 8;
    const int mbh = blockIdx.x & 1;
    const int mb  = mbh * 32;
    unsigned* cnt = &g_cnt2[mbh][0];

    // preload W slice + gx(0)
    {
#pragma unroll
        for (int i = 0; i < 16; i++) {
            int q = i * 256 + tid;
            int lrow = q >> 7, c16 = q & 127;
            int g = lrow >> 3, jl = lrow & 7;
            CP_ASYNC16(sb + W_OFF + lrow * 2048 + (((uint32_t)(c16 ^ (lrow & 7))) << 4),
                       (const void*)(g_w2 + (size_t)(g * 512 + j0 + jl) * 1024 + c16 * 8));
        }
        {
            int n = tid >> 3, c = tid & 7;
            int g = n >> 3, jl = n & 7;
            CP_ASYNC16(sb + GX_OFF + (uint32_t)(n * 32 + c * 4) * 4,
                       (const void*)(g_gx + (size_t)(g * 512 + j0 + jl) * 64 + mb + c * 4));
        }
        CP_COMMIT();
        CP_WAIT0();
    }
    __syncthreads();

    const int pjl = tid >> 5;
    const int pb  = tid & 31;
    float bias[4];
#pragma unroll
    for (int g = 0; g < 4; g++) bias[g] = bh[g * 512 + j0 + pjl];
    float cs = 0.f;

    const int mt = wid & 1, ng = wid >> 1;
    const int brow = ng * 8 + (lane & 7);
    const int bq   = lane >> 3;
    const uint32_t bbase = sb + W_OFF + brow * 2048;
    const uint32_t bph = (uint32_t)(brow & 7);

    // hoist w_hi B-fragments to registers (invariant across all steps)
    uint32_t bhi[32][2];
#pragma unroll
    for (int ksd2 = 0; ksd2 < 16; ksd2++) {
        uint32_t r0, r1, r2, r3;
        LDSM_X4(r0, r1, r2, r3, bbase + (((uint32_t)(ksd2 * 4 + bq) ^ bph) << 4));
        bhi[2 * ksd2][0] = r0;     bhi[2 * ksd2][1] = r1;
        bhi[2 * ksd2 + 1][0] = r2; bhi[2 * ksd2 + 1][1] = r3;
    }

    // fragment-buffer bases (uint4 units)
    const uint4* fh0 = g_fragh + mbh * 2048 + mt * 1024 + lane;
    const uint4* fl0 = g_fragl + mbh * 2048 + mt * 1024 + lane;

    // producer pack constants
    const int kcj   = j0 >> 4;
    const int jhalf = (j0 >> 3) & 1;

    for (int t = 0; t < S_; t++) {
        float acc[4][4];
#pragma unroll
        for (int i = 0; i < 4; i++)
#pragma unroll
            for (int q = 0; q < 4; q++) acc[i][q] = 0.f;

        const uint4* ph = fh0 + (t & 1) * 4096;
        const uint4* pl = fl0 + (t & 1) * 4096;

#pragma unroll
        for (int ksd2 = 0; ksd2 < 16; ksd2++) {
            const int kc0 = 2 * ksd2;
            uint4 av0, av1, lv0, lv1;
            LDG128CG(av0, ph + kc0 * 32);
            LDG128CG(av1, ph + (kc0 + 1) * 32);
            LDG128CG(lv0, pl + kc0 * 32);
            LDG128CG(lv1, pl + (kc0 + 1) * 32);
            uint32_t wl0, wl1, wl2, wl3;
            LDSM_X4(wl0, wl1, wl2, wl3,
                    bbase + (((uint32_t)(64 + ksd2 * 4 + bq) ^ bph) << 4));
            uint32_t a0[4] = { av0.x, av0.y, av0.z, av0.w };
            uint32_t a1[4] = { av1.x, av1.y, av1.z, av1.w };
            uint32_t l0[4] = { lv0.x, lv0.y, lv0.z, lv0.w };
            uint32_t l1[4] = { lv1.x, lv1.y, lv1.z, lv1.w };
            uint32_t wlo0[2] = { wl0, wl1 }, wlo1[2] = { wl2, wl3 };
            MMA16816(acc[0], a0, bhi[kc0]);
            MMA16816(acc[1], a1, bhi[kc0 + 1]);
            MMA16816(acc[2], a0, wlo0);
            MMA16816(acc[3], a1, wlo1);
            MMA16816(acc[0], l0, bhi[kc0]);
            MMA16816(acc[1], l1, bhi[kc0 + 1]);
        }

        // frags -> gates_s[n][m]
        {
            const int fm = mt * 16 + (lane >> 2);
            const int fn = ng * 8 + 2 * (lane & 3);
            float r0 = acc[0][0] + acc[1][0] + acc[2][0] + acc[3][0];
            float r1 = acc[0][1] + acc[1][1] + acc[2][1] + acc[3][1];
            float r2 = acc[0][2] + acc[1][2] + acc[2][2] + acc[3][2];
            float r3 = acc[0][3] + acc[1][3] + acc[2][3] + acc[3][3];
            gates_s[fn * 34 + fm]           = r0;
            gates_s[(fn + 1) * 34 + fm]     = r1;
            gates_s[fn * 34 + fm + 8]       = r2;
            gates_s[(fn + 1) * 34 + fm + 8] = r3;
        }
        CP_WAIT0();        // gx(t) group complete
        __syncthreads();

        // fused pointwise
        float pre[4];
#pragma unroll
        for (int g = 0; g < 4; g++) {
            int n = g * 8 + pjl;
            pre[g] = gates_s[n * 34 + pb] + gx_s[n * 32 + pb] + bias[g];
        }
        float iv = 1.f / (1.f + __expf(-pre[0]));
        float fv = 1.f / (1.f + __expf(-pre[1]));
        float gv = tanhf(pre[2]);
        float ov = 1.f / (1.f + __expf(-pre[3]));
        cs = fv * cs + iv * gv;
        float hv = ov * tanhf(cs);

        if (t == S_ - 1) {
            const size_t ob = (size_t)B_ * S_ * H4_;
            out[((size_t)(mb + pb) * S_ + t) * H4_ + j0 + pjl] = hv;
            out[ob + (size_t)(mb + pb) * H4_ + j0 + pjl] = hv;
            out[ob + (size_t)B_ * H4_ + (size_t)(mb + pb) * H4_ + j0 + pjl] = cs;
            continue;
        }

        // stage h (hi/lo fp16 + fp32 for out)
        {
            __half hh = __float2half_rn(hv);
            __half hl = __float2half_rn(hv - __half2float(hh));
            hst[pb * 8 + pjl]       = hh;
            hst[256 + pb * 8 + pjl] = hl;
            hstf[pb * 8 + pjl]      = hv;
        }
        __syncthreads();

        // publish h(t+1) in fragment layout: CTA owns 8-byte half of each lane record
        const int buf = (t + 1) & 1;
        if (tid < 128) {
            const int hl_sel = tid >> 6;             // 0 = hi, 1 = lo
            const int pmt = (tid >> 5) & 1, L = tid & 31;
            const int b0r = pmt * 16 + (L >> 2), b1r = b0r + 8;
            const int jc = (L & 3) * 2;
            const __half* src = hst + hl_sel * 256;
            uint32_t a0 = *(const uint32_t*)&src[b0r * 8 + jc];
            uint32_t a1 = *(const uint32_t*)&src[b1r * 8 + jc];
            uint4* base = (hl_sel ? g_fragl : g_fragh);
            size_t idx = (size_t)buf * 4096 + (size_t)mbh * 2048 + (size_t)pmt * 1024
                       + (size_t)kcj * 32 + L;
            char* dst = (char*)(base + idx) + jhalf * 8;
            asm volatile("st.global.v2.b32 [%0], {%1,%2};"
                         :: "l"(dst), "r"(a0), "r"(a1) : "memory");
        }
        __syncthreads();

        // gx(t+1) prefetch (independent of barrier)
        {
            int n = tid >> 3, c = tid & 7;
            int g = n >> 3, jl = n & 7;
            CP_ASYNC16(sb + GX_OFF + (uint32_t)(n * 32 + c * 4) * 4,
                       (const void*)(g_gx + (size_t)(t + 1) * (G_ * B_)
                                     + (size_t)(g * 512 + j0 + jl) * 64 + mb + c * 4));
        }
        CP_COMMIT();

        // arrive + single-thread poll; out stores overlap in warp 1
        if (tid == 0)
            asm volatile("red.release.gpu.global.add.u32 [%0], %1;"
                         :: "l"(cnt), "r"(1u) : "memory");
        if (tid >= 32 && tid < 64) {
            int b = tid - 32;
            float* dst = out + ((size_t)(mb + b) * S_ + t) * H4_ + j0;
            *(float4*)dst       = *(float4*)(hstf + b * 8);
            *(float4*)(dst + 4) = *(float4*)(hstf + b * 8 + 4);
        }
        if (tid == 0) {
            const unsigned tgt = (unsigned)(t + 1) * 64u;
            unsigned v;
            do {
                asm volatile("ld.acquire.gpu.global.u32 %0, [%1];"
                             : "=r"(v) : "l"(cnt) : "memory");
            } while (v < tgt);
        }
        __syncthreads();
    }
}

extern "C" void kernel_launch(void* const* d_in, const int* in_sizes, int n_in,
                              void* d_out, int out_size) {
    const float* X  = (const float*)d_in[0];
    const float* Wi = (const float*)d_in[1];
    const float* Wh = (const float*)d_in[2];
    const float* bi = (const float*)d_in[3];
    const float* bh = (const float*)d_in[4];
    float* out = (float*)d_out;

    cudaFuncSetAttribute(gemm_hmma_kernel, cudaFuncAttributeMaxDynamicSharedMemorySize, SMEM_GEMM);
    cudaFuncSetAttribute(lstm_kernel, cudaFuncAttributeMaxDynamicSharedMemorySize, SMEM_LSTM);

    conv_a_kernel<<<32768, 256>>>(X);
    conv_b_kernel<<<1024, 256>>>(Wi);
    conv_w_kernel<<<1024, 256>>>(Wh);
    gemm_hmma_kernel<<<dim3(16, 512), 256, SMEM_GEMM>>>(bi);
    lstm_kernel<<<NCTA2, 256, SMEM_LSTM>>>(bh, out);
}